// round 4
// baseline (speedup 1.0000x reference)
#include <cuda_runtime.h>
#include <cuda_bf16.h>
#include <math.h>

// Problem constants (fixed by the reference)
#define BATCH 2
#define SEQ   2048
#define DMODEL 1024
#define NHEAD 16
#define HD    64          // head dim
#define QKV_ROW (3*DMODEL)

// Scratch (allocation-free rule: __device__ globals)
__device__ float g_qkv[(size_t)BATCH*SEQ*QKV_ROW];   // [B,S,3D]
__device__ float g_att[(size_t)BATCH*SEQ*DMODEL];    // [B,S,D] merged heads

// ---------------------------------------------------------------------------
// Tiled fp32 GEMM with bias:  C[M,N] = A[M,K] @ W[K,N] + bias[N]
// BM=128, BN=128, BK=16, 256 threads, 8x8 micro-tile per thread.
// ---------------------------------------------------------------------------
__global__ __launch_bounds__(256, 2)
void gemm_bias_kernel(const float* __restrict__ A,
                      const float* __restrict__ W,
                      const float* __restrict__ bias,
                      float* __restrict__ C,
                      int M, int N, int K)
{
    const int BM = 128, BN = 128, BK = 16;
    __shared__ float As[BK][BM];      // k-major
    __shared__ float Bs[BK][BN];

    int tid = threadIdx.x;            // 0..255
    int tx = tid & 15;                // 16 col-groups of 8
    int ty = tid >> 4;                // 16 row-groups of 8
    int row0 = blockIdx.y * BM;
    int col0 = blockIdx.x * BN;

    float acc[8][8];
    #pragma unroll
    for (int i = 0; i < 8; i++)
        #pragma unroll
        for (int j = 0; j < 8; j++)
            acc[i][j] = 0.f;

    for (int k0 = 0; k0 < K; k0 += BK) {
        // Load A tile (128 rows x 16 k), transpose into As[k][row]
        #pragma unroll
        for (int it = 0; it < 2; it++) {
            int idx = tid + it * 256;          // 0..511 float4 slots
            int r  = idx >> 2;                 // 0..127
            int kc = (idx & 3) * 4;            // 0,4,8,12
            float4 v = *(const float4*)&A[(size_t)(row0 + r) * K + k0 + kc];
            As[kc + 0][r] = v.x;
            As[kc + 1][r] = v.y;
            As[kc + 2][r] = v.z;
            As[kc + 3][r] = v.w;
        }
        // Load B tile (16 k x 128 cols), coalesced
        #pragma unroll
        for (int it = 0; it < 2; it++) {
            int idx = tid + it * 256;          // 0..511 float4 slots
            int r = idx >> 5;                  // 0..15
            int c = (idx & 31) * 4;            // 0..124
            *(float4*)&Bs[r][c] = *(const float4*)&W[(size_t)(k0 + r) * N + col0 + c];
        }
        __syncthreads();

        #pragma unroll
        for (int kk = 0; kk < BK; kk++) {
            float a[8], b[8];
            *(float4*)&a[0] = *(const float4*)&As[kk][ty * 8 + 0];
            *(float4*)&a[4] = *(const float4*)&As[kk][ty * 8 + 4];
            *(float4*)&b[0] = *(const float4*)&Bs[kk][tx * 8 + 0];
            *(float4*)&b[4] = *(const float4*)&Bs[kk][tx * 8 + 4];
            #pragma unroll
            for (int i = 0; i < 8; i++)
                #pragma unroll
                for (int j = 0; j < 8; j++)
                    acc[i][j] += a[i] * b[j];
        }
        __syncthreads();
    }

    #pragma unroll
    for (int i = 0; i < 8; i++) {
        int r = row0 + ty * 8 + i;
        #pragma unroll
        for (int j = 0; j < 8; j += 4) {
            int c = col0 + tx * 8 + j;
            float4 o;
            o.x = acc[i][j + 0] + bias[c + 0];
            o.y = acc[i][j + 1] + bias[c + 1];
            o.z = acc[i][j + 2] + bias[c + 2];
            o.w = acc[i][j + 3] + bias[c + 3];
            *(float4*)&C[(size_t)r * N + c] = o;
        }
    }
}

// ---------------------------------------------------------------------------
// Causal flash attention, fp32.
// Thread-per-query-row: 128 rows per block, q/o register-resident.
// grid = (S/128, NHEAD, BATCH), block = 128 threads.
// qkv layout per row: [Q(0:1024) | K(1024:2048) | V(2048:3072)]
// ---------------------------------------------------------------------------
__global__ __launch_bounds__(128, 3)
void attn_kernel(const float* __restrict__ qkv, float* __restrict__ out)
{
    int qt = blockIdx.x;
    int h  = blockIdx.y;
    int b  = blockIdx.z;
    int tid = threadIdx.x;
    int qi = qt * 128 + tid;          // global query index in [0, SEQ)

    __shared__ float Ks[64][HD];
    __shared__ float Vs[64][HD];

    // Load this thread's q row into registers
    const float* qrow = qkv + ((size_t)(b * SEQ + qi)) * QKV_ROW + h * HD;
    float q[HD], o[HD];
    #pragma unroll
    for (int d = 0; d < HD; d += 4) {
        float4 v = *(const float4*)&qrow[d];
        q[d + 0] = v.x; q[d + 1] = v.y; q[d + 2] = v.z; q[d + 3] = v.w;
    }
    #pragma unroll
    for (int d = 0; d < HD; d++) o[d] = 0.f;

    float m = -INFINITY;
    float l = 0.f;

    int ntiles = 2 * (qt + 1);        // key tiles of 64 covering [0, qt*128+128)
    for (int t = 0; t < ntiles; t++) {
        int kbase = t * 64;
        __syncthreads();              // previous tile fully consumed
        // Stage K and V tiles: 64 rows x 64 floats each (1024 float4 total each)
        for (int i = tid; i < 64 * 16; i += 128) {
            int r = i >> 4;
            int c = (i & 15) * 4;
            const float* src = qkv + ((size_t)(b * SEQ + kbase + r)) * QKV_ROW
                             + DMODEL + h * HD + c;
            *(float4*)&Ks[r][c] = *(const float4*)src;
            *(float4*)&Vs[r][c] = *(const float4*)(src + DMODEL);
        }
        __syncthreads();

        int jmax = qi - kbase + 1;
        if (jmax > 64) jmax = 64;
        for (int j = 0; j < jmax; j++) {
            // s = (q . k_j) / sqrt(hd)
            float s = 0.f;
            #pragma unroll
            for (int d = 0; d < HD; d += 4) {
                float4 kv = *(const float4*)&Ks[j][d];
                s += q[d + 0] * kv.x + q[d + 1] * kv.y
                   + q[d + 2] * kv.z + q[d + 3] * kv.w;
            }
            s *= 0.125f;

            if (s > m) {              // rare after warmup: rescale running state
                float corr = __expf(m - s);   // exp(-inf)=0 handles first key
                l *= corr;
                #pragma unroll
                for (int d = 0; d < HD; d++) o[d] *= corr;
                m = s;
            }
            float p = __expf(s - m);
            l += p;
            #pragma unroll
            for (int d = 0; d < HD; d += 4) {
                float4 vv = *(const float4*)&Vs[j][d];
                o[d + 0] += p * vv.x; o[d + 1] += p * vv.y;
                o[d + 2] += p * vv.z; o[d + 3] += p * vv.w;
            }
        }
    }

    float inv = 1.f / l;
    float* orow = out + ((size_t)(b * SEQ + qi)) * DMODEL + h * HD;
    #pragma unroll
    for (int d = 0; d < HD; d += 4) {
        float4 v;
        v.x = o[d + 0] * inv; v.y = o[d + 1] * inv;
        v.z = o[d + 2] * inv; v.w = o[d + 3] * inv;
        *(float4*)&orow[d] = v;
    }
}

// ---------------------------------------------------------------------------
// Launch
// ---------------------------------------------------------------------------
extern "C" void kernel_launch(void* const* d_in, const int* in_sizes, int n_in,
                              void* d_out, int out_size)
{
    const float* hidden = (const float*)d_in[0];   // [B,S,D]
    const float* W_attn = (const float*)d_in[1];   // [D,3D]
    const float* b_attn = (const float*)d_in[2];   // [3D]
    const float* W_proj = (const float*)d_in[3];   // [D,D]
    const float* b_proj = (const float*)d_in[4];   // [D]
    float* out = (float*)d_out;                    // [B,S,D]

    float* qkv = nullptr;
    float* att = nullptr;
    cudaGetSymbolAddress((void**)&qkv, g_qkv);
    cudaGetSymbolAddress((void**)&att, g_att);

    const int M = BATCH * SEQ;   // 4096

    // 1) QKV projection: [4096,1024] @ [1024,3072] + b
    {
        dim3 grid(3 * DMODEL / 128, M / 128);  // (24, 32)
        gemm_bias_kernel<<<grid, 256>>>(hidden, W_attn, b_attn, qkv,
                                        M, 3 * DMODEL, DMODEL);
    }
    // 2) Causal attention
    {
        dim3 grid(SEQ / 128, NHEAD, BATCH);    // (16, 16, 2)
        attn_kernel<<<grid, 128>>>(qkv, att);
    }
    // 3) Output projection: [4096,1024] @ [1024,1024] + b
    {
        dim3 grid(DMODEL / 128, M / 128);      // (8, 32)
        gemm_bias_kernel<<<grid, 256>>>(att, W_proj, b_proj, out,
                                        M, DMODEL, DMODEL);
    }
}

// round 5
// speedup vs baseline: 1.2677x; 1.2677x over previous
#include <cuda_runtime.h>
#include <cuda_bf16.h>
#include <math.h>

// Problem constants (fixed by the reference)
#define BATCH 2
#define SEQ   2048
#define DMODEL 1024
#define NHEAD 16
#define HD    64          // head dim
#define QKV_ROW (3*DMODEL)

// Scratch (allocation-free rule: __device__ globals)
__device__ float g_qkv[(size_t)BATCH*SEQ*QKV_ROW];   // [B,S,3D]
__device__ float g_att[(size_t)BATCH*SEQ*DMODEL];    // [B,S,D] merged heads

// ---------------------------------------------------------------------------
// Tiled fp32 GEMM with bias, double-buffered smem:
//   C[M,N] = A[M,K] @ W[K,N] + bias[N]
// BM=128, BN=128, BK=16, 256 threads, 8x8 micro-tile per thread.
// ---------------------------------------------------------------------------
__global__ __launch_bounds__(256, 2)
void gemm_bias_kernel(const float* __restrict__ A,
                      const float* __restrict__ W,
                      const float* __restrict__ bias,
                      float* __restrict__ C,
                      int M, int N, int K)
{
    const int BM = 128, BN = 128, BK = 16;
    __shared__ float As[2][BK][BM];      // k-major
    __shared__ float Bs[2][BK][BN];

    int tid = threadIdx.x;            // 0..255
    int tx = tid & 15;                // 16 col-groups of 8
    int ty = tid >> 4;                // 16 row-groups of 8
    int row0 = blockIdx.y * BM;
    int col0 = blockIdx.x * BN;

    // Per-thread load coordinates (2 float4 slots each for A and B tiles)
    int aR[2], aK[2], bR[2], bC[2];
    #pragma unroll
    for (int it = 0; it < 2; it++) {
        int idx = tid + it * 256;     // 0..511
        aR[it] = idx >> 2;            // 0..127
        aK[it] = (idx & 3) * 4;       // 0,4,8,12
        bR[it] = idx >> 5;            // 0..15
        bC[it] = (idx & 31) * 4;      // 0..124
    }

    float acc[8][8];
    #pragma unroll
    for (int i = 0; i < 8; i++)
        #pragma unroll
        for (int j = 0; j < 8; j++)
            acc[i][j] = 0.f;

    float4 aS[2], bS[2];

    // Prologue: load tile 0 into buffer 0
    #pragma unroll
    for (int it = 0; it < 2; it++) {
        aS[it] = *(const float4*)&A[(size_t)(row0 + aR[it]) * K + aK[it]];
        bS[it] = *(const float4*)&W[(size_t)(bR[it]) * N + col0 + bC[it]];
    }
    #pragma unroll
    for (int it = 0; it < 2; it++) {
        As[0][aK[it] + 0][aR[it]] = aS[it].x;
        As[0][aK[it] + 1][aR[it]] = aS[it].y;
        As[0][aK[it] + 2][aR[it]] = aS[it].z;
        As[0][aK[it] + 3][aR[it]] = aS[it].w;
        *(float4*)&Bs[0][bR[it]][bC[it]] = bS[it];
    }
    __syncthreads();

    int buf = 0;
    for (int k0 = 0; k0 < K; k0 += BK) {
        bool has_next = (k0 + BK) < K;
        // Issue next tile's global loads early (latency overlapped with compute)
        if (has_next) {
            #pragma unroll
            for (int it = 0; it < 2; it++) {
                aS[it] = *(const float4*)&A[(size_t)(row0 + aR[it]) * K + (k0 + BK) + aK[it]];
                bS[it] = *(const float4*)&W[(size_t)(k0 + BK + bR[it]) * N + col0 + bC[it]];
            }
        }

        // Compute on current buffer
        #pragma unroll
        for (int kk = 0; kk < BK; kk++) {
            float a[8], b[8];
            *(float4*)&a[0] = *(const float4*)&As[buf][kk][ty * 8 + 0];
            *(float4*)&a[4] = *(const float4*)&As[buf][kk][ty * 8 + 4];
            *(float4*)&b[0] = *(const float4*)&Bs[buf][kk][tx * 8 + 0];
            *(float4*)&b[4] = *(const float4*)&Bs[buf][kk][tx * 8 + 4];
            #pragma unroll
            for (int i = 0; i < 8; i++)
                #pragma unroll
                for (int j = 0; j < 8; j++)
                    acc[i][j] += a[i] * b[j];
        }

        // Store staged tile into the other buffer
        if (has_next) {
            int nb = buf ^ 1;
            #pragma unroll
            for (int it = 0; it < 2; it++) {
                As[nb][aK[it] + 0][aR[it]] = aS[it].x;
                As[nb][aK[it] + 1][aR[it]] = aS[it].y;
                As[nb][aK[it] + 2][aR[it]] = aS[it].z;
                As[nb][aK[it] + 3][aR[it]] = aS[it].w;
                *(float4*)&Bs[nb][bR[it]][bC[it]] = bS[it];
            }
        }
        __syncthreads();
        buf ^= 1;
    }

    #pragma unroll
    for (int i = 0; i < 8; i++) {
        int r = row0 + ty * 8 + i;
        #pragma unroll
        for (int j = 0; j < 8; j += 4) {
            int c = col0 + tx * 8 + j;
            float4 o;
            o.x = acc[i][j + 0] + bias[c + 0];
            o.y = acc[i][j + 1] + bias[c + 1];
            o.z = acc[i][j + 2] + bias[c + 2];
            o.w = acc[i][j + 3] + bias[c + 3];
            *(float4*)&C[(size_t)r * N + c] = o;
        }
    }
}

// ---------------------------------------------------------------------------
// Causal flash attention, fp32, ILP-restructured.
// Thread-per-query-row: 128 rows per block, q/o register-resident.
// Keys processed in chunks of 4: 4 independent dot chains (2 accumulators
// each), branch-free online-softmax rescale once per chunk.
// grid = (S/128, NHEAD, BATCH), block = 128 threads.
// qkv layout per row: [Q(0:1024) | K(1024:2048) | V(2048:3072)]
// ---------------------------------------------------------------------------
__global__ __launch_bounds__(128, 3)
void attn_kernel(const float* __restrict__ qkv, float* __restrict__ out)
{
    // Heavy blocks (large qt => most key tiles) scheduled first
    int qt = (int)gridDim.x - 1 - (int)blockIdx.x;
    int h  = blockIdx.y;
    int b  = blockIdx.z;
    int tid = threadIdx.x;
    int qi = qt * 128 + tid;          // global query index in [0, SEQ)

    __shared__ float Ks[64][HD];
    __shared__ float Vs[64][HD];

    // Load this thread's q row into registers
    const float* qrow = qkv + ((size_t)(b * SEQ + qi)) * QKV_ROW + h * HD;
    float q[HD], o[HD];
    #pragma unroll
    for (int d = 0; d < HD; d += 4) {
        float4 v = *(const float4*)&qrow[d];
        q[d + 0] = v.x; q[d + 1] = v.y; q[d + 2] = v.z; q[d + 3] = v.w;
    }
    #pragma unroll
    for (int d = 0; d < HD; d++) o[d] = 0.f;

    float m = -INFINITY;
    float l = 0.f;

    int ntiles = 2 * (qt + 1);        // key tiles of 64 covering [0, qt*128+128)
    for (int t = 0; t < ntiles; t++) {
        int kbase = t * 64;
        __syncthreads();              // previous tile fully consumed
        // Stage K and V tiles: 64 rows x 64 floats each
        for (int i = tid; i < 64 * 16; i += 128) {
            int r = i >> 4;
            int c = (i & 15) * 4;
            const float* src = qkv + ((size_t)(b * SEQ + kbase + r)) * QKV_ROW
                             + DMODEL + h * HD + c;
            *(float4*)&Ks[r][c] = *(const float4*)src;
            *(float4*)&Vs[r][c] = *(const float4*)(src + DMODEL);
        }
        __syncthreads();

        int jmax = qi - kbase + 1;    // causal bound within tile
        if (jmax > 64) jmax = 64;

        for (int j0 = 0; j0 < jmax; j0 += 4) {
            // ---- 4 independent dot products, 2 accumulators each ----
            float s[4];
            #pragma unroll
            for (int jj = 0; jj < 4; jj++) {
                const float* kr = Ks[j0 + jj];
                float a0 = 0.f, a1 = 0.f;
                #pragma unroll
                for (int d = 0; d < HD; d += 8) {
                    float4 k0 = *(const float4*)&kr[d];
                    float4 k1 = *(const float4*)&kr[d + 4];
                    a0 = fmaf(q[d+0], k0.x, fmaf(q[d+1], k0.y,
                         fmaf(q[d+2], k0.z, fmaf(q[d+3], k0.w, a0))));
                    a1 = fmaf(q[d+4], k1.x, fmaf(q[d+5], k1.y,
                         fmaf(q[d+6], k1.z, fmaf(q[d+7], k1.w, a1))));
                }
                float sv = (a0 + a1) * 0.125f;
                // causal mask within chunk (branch-free: p becomes exp(-inf)=0)
                s[jj] = (j0 + jj < jmax) ? sv : -INFINITY;
            }

            // ---- branch-free online softmax update ----
            float mn = fmaxf(fmaxf(fmaxf(s[0], s[1]), fmaxf(s[2], s[3])), m);
            float corr = __expf(m - mn);   // ==1 if max unchanged; ==0 from -inf start
            m = mn;
            float p0 = __expf(s[0] - m);
            float p1 = __expf(s[1] - m);
            float p2 = __expf(s[2] - m);
            float p3 = __expf(s[3] - m);
            l = fmaf(l, corr, (p0 + p1) + (p2 + p3));

            #pragma unroll
            for (int d = 0; d < HD; d += 4) {
                float4 v0 = *(const float4*)&Vs[j0 + 0][d];
                float4 v1 = *(const float4*)&Vs[j0 + 1][d];
                float4 v2 = *(const float4*)&Vs[j0 + 2][d];
                float4 v3 = *(const float4*)&Vs[j0 + 3][d];
                o[d+0] = fmaf(p3, v3.x, fmaf(p2, v2.x, fmaf(p1, v1.x,
                         fmaf(p0, v0.x, o[d+0] * corr))));
                o[d+1] = fmaf(p3, v3.y, fmaf(p2, v2.y, fmaf(p1, v1.y,
                         fmaf(p0, v0.y, o[d+1] * corr))));
                o[d+2] = fmaf(p3, v3.z, fmaf(p2, v2.z, fmaf(p1, v1.z,
                         fmaf(p0, v0.z, o[d+2] * corr))));
                o[d+3] = fmaf(p3, v3.w, fmaf(p2, v2.w, fmaf(p1, v1.w,
                         fmaf(p0, v0.w, o[d+3] * corr))));
            }
        }
    }

    float inv = 1.f / l;
    float* orow = out + ((size_t)(b * SEQ + qi)) * DMODEL + h * HD;
    #pragma unroll
    for (int d = 0; d < HD; d += 4) {
        float4 v;
        v.x = o[d + 0] * inv; v.y = o[d + 1] * inv;
        v.z = o[d + 2] * inv; v.w = o[d + 3] * inv;
        *(float4*)&orow[d] = v;
    }
}

// ---------------------------------------------------------------------------
// Launch
// ---------------------------------------------------------------------------
extern "C" void kernel_launch(void* const* d_in, const int* in_sizes, int n_in,
                              void* d_out, int out_size)
{
    const float* hidden = (const float*)d_in[0];   // [B,S,D]
    const float* W_attn = (const float*)d_in[1];   // [D,3D]
    const float* b_attn = (const float*)d_in[2];   // [3D]
    const float* W_proj = (const float*)d_in[3];   // [D,D]
    const float* b_proj = (const float*)d_in[4];   // [D]
    float* out = (float*)d_out;                    // [B,S,D]

    float* qkv = nullptr;
    float* att = nullptr;
    cudaGetSymbolAddress((void**)&qkv, g_qkv);
    cudaGetSymbolAddress((void**)&att, g_att);

    const int M = BATCH * SEQ;   // 4096

    // 1) QKV projection: [4096,1024] @ [1024,3072] + b
    {
        dim3 grid(3 * DMODEL / 128, M / 128);  // (24, 32)
        gemm_bias_kernel<<<grid, 256>>>(hidden, W_attn, b_attn, qkv,
                                        M, 3 * DMODEL, DMODEL);
    }
    // 2) Causal attention
    {
        dim3 grid(SEQ / 128, NHEAD, BATCH);    // (16, 16, 2)
        attn_kernel<<<grid, 128>>>(qkv, att);
    }
    // 3) Output projection: [4096,1024] @ [1024,1024] + b
    {
        dim3 grid(DMODEL / 128, M / 128);      // (8, 32)
        gemm_bias_kernel<<<grid, 256>>>(att, W_proj, b_proj, out,
                                        M, DMODEL, DMODEL);
    }
}

// round 6
// speedup vs baseline: 1.2939x; 1.0207x over previous
#include <cuda_runtime.h>
#include <cuda_bf16.h>
#include <math.h>

// Problem constants (fixed by the reference)
#define BATCH 2
#define SEQ   2048
#define DMODEL 1024
#define NHEAD 16
#define HD    64          // head dim
#define QKV_ROW (3*DMODEL)

typedef unsigned long long ull;

// ---- packed f32x2 helpers (sm_103a) ---------------------------------------
__device__ __forceinline__ ull f2_fma(ull a, ull b, ull c) {
    ull d;
    asm("fma.rn.f32x2 %0, %1, %2, %3;" : "=l"(d) : "l"(a), "l"(b), "l"(c));
    return d;
}
__device__ __forceinline__ ull f2_mul(ull a, ull b) {
    ull d;
    asm("mul.rn.f32x2 %0, %1, %2;" : "=l"(d) : "l"(a), "l"(b));
    return d;
}
__device__ __forceinline__ ull f2_add(ull a, ull b) {
    ull d;
    asm("add.rn.f32x2 %0, %1, %2;" : "=l"(d) : "l"(a), "l"(b));
    return d;
}
__device__ __forceinline__ ull f2_pack(float lo, float hi) {
    ull d;
    asm("mov.b64 %0, {%1, %2};" : "=l"(d) : "f"(lo), "f"(hi));
    return d;
}
__device__ __forceinline__ float2 f2_unpack(ull v) {
    float lo, hi;
    asm("mov.b64 {%0, %1}, %2;" : "=f"(lo), "=f"(hi) : "l"(v));
    return make_float2(lo, hi);
}

// Scratch (allocation-free rule: __device__ globals)
__device__ float g_qkv[(size_t)BATCH*SEQ*QKV_ROW];   // [B,S,3D]
__device__ float g_att[(size_t)BATCH*SEQ*DMODEL];    // [B,S,D] merged heads

// ---------------------------------------------------------------------------
// Tiled fp32 GEMM with bias, f32x2 inner product:
//   C[M,N] = A[M,K] @ W[K,N] + bias[N]
// BM=128, BN=128, BK=16, 256 threads, 8x8 micro-tile per thread
// (accumulators held as 8x4 packed f32x2 pairs).
// ---------------------------------------------------------------------------
__global__ __launch_bounds__(256, 2)
void gemm_bias_kernel(const float* __restrict__ A,
                      const float* __restrict__ W,
                      const float* __restrict__ bias,
                      float* __restrict__ C,
                      int M, int N, int K)
{
    const int BM = 128, BN = 128, BK = 16;
    __shared__ float As[BK][BM];      // k-major
    __shared__ float Bs[BK][BN];

    int tid = threadIdx.x;            // 0..255
    int tx = tid & 15;                // 16 col-groups of 8
    int ty = tid >> 4;                // 16 row-groups of 8
    int row0 = blockIdx.y * BM;
    int col0 = blockIdx.x * BN;

    ull acc[8][4];
    #pragma unroll
    for (int i = 0; i < 8; i++)
        #pragma unroll
        for (int j = 0; j < 4; j++)
            acc[i][j] = 0ull;         // (0.0f, 0.0f)

    for (int k0 = 0; k0 < K; k0 += BK) {
        // Load A tile (128 rows x 16 k), transpose into As[k][row]
        #pragma unroll
        for (int it = 0; it < 2; it++) {
            int idx = tid + it * 256;          // 0..511 float4 slots
            int r  = idx >> 2;                 // 0..127
            int kc = (idx & 3) * 4;            // 0,4,8,12
            float4 v = *(const float4*)&A[(size_t)(row0 + r) * K + k0 + kc];
            As[kc + 0][r] = v.x;
            As[kc + 1][r] = v.y;
            As[kc + 2][r] = v.z;
            As[kc + 3][r] = v.w;
        }
        // Load B tile (16 k x 128 cols), coalesced
        #pragma unroll
        for (int it = 0; it < 2; it++) {
            int idx = tid + it * 256;          // 0..511 float4 slots
            int r = idx >> 5;                  // 0..15
            int c = (idx & 31) * 4;            // 0..124
            *(float4*)&Bs[r][c] = *(const float4*)&W[(size_t)(k0 + r) * N + col0 + c];
        }
        __syncthreads();

        #pragma unroll
        for (int kk = 0; kk < BK; kk++) {
            float a[8];
            *(float4*)&a[0] = *(const float4*)&As[kk][ty * 8 + 0];
            *(float4*)&a[4] = *(const float4*)&As[kk][ty * 8 + 4];
            float4 b0 = *(const float4*)&Bs[kk][tx * 8 + 0];
            float4 b1 = *(const float4*)&Bs[kk][tx * 8 + 4];
            ull bp[4];
            bp[0] = f2_pack(b0.x, b0.y);
            bp[1] = f2_pack(b0.z, b0.w);
            bp[2] = f2_pack(b1.x, b1.y);
            bp[3] = f2_pack(b1.z, b1.w);
            #pragma unroll
            for (int i = 0; i < 8; i++) {
                ull ad = f2_pack(a[i], a[i]);
                #pragma unroll
                for (int j = 0; j < 4; j++)
                    acc[i][j] = f2_fma(ad, bp[j], acc[i][j]);
            }
        }
        __syncthreads();
    }

    #pragma unroll
    for (int i = 0; i < 8; i++) {
        int r = row0 + ty * 8 + i;
        #pragma unroll
        for (int jp = 0; jp < 2; jp++) {       // two float4 stores
            int c = col0 + tx * 8 + jp * 4;
            float2 p0 = f2_unpack(acc[i][jp * 2 + 0]);
            float2 p1 = f2_unpack(acc[i][jp * 2 + 1]);
            float4 o;
            o.x = p0.x + bias[c + 0];
            o.y = p0.y + bias[c + 1];
            o.z = p1.x + bias[c + 2];
            o.w = p1.y + bias[c + 3];
            *(float4*)&C[(size_t)r * N + c] = o;
        }
    }
}

// ---------------------------------------------------------------------------
// Causal flash attention, fp32, f32x2 packed math.
// Thread-per-query-row: 128 rows per block, q/o register-resident as pairs.
// Keys in chunks of 4; branch-free online softmax per chunk.
// grid = (S/128, NHEAD, BATCH), block = 128 threads.
// qkv layout per row: [Q(0:1024) | K(1024:2048) | V(2048:3072)]
// ---------------------------------------------------------------------------
__global__ __launch_bounds__(128, 3)
void attn_kernel(const float* __restrict__ qkv, float* __restrict__ out)
{
    // Heavy blocks (large qt => most key tiles) scheduled first
    int qt = (int)gridDim.x - 1 - (int)blockIdx.x;
    int h  = blockIdx.y;
    int b  = blockIdx.z;
    int tid = threadIdx.x;
    int qi = qt * 128 + tid;          // global query index in [0, SEQ)

    __shared__ float Ks[64][HD];
    __shared__ float Vs[64][HD];

    // Load this thread's q row into packed pairs
    const float* qrow = qkv + ((size_t)(b * SEQ + qi)) * QKV_ROW + h * HD;
    ull qp[HD/2], op[HD/2];
    #pragma unroll
    for (int d = 0; d < HD; d += 4) {
        float4 v = *(const float4*)&qrow[d];
        qp[d/2 + 0] = f2_pack(v.x, v.y);
        qp[d/2 + 1] = f2_pack(v.z, v.w);
    }
    #pragma unroll
    for (int i = 0; i < HD/2; i++) op[i] = 0ull;

    float m = -INFINITY;
    float l = 0.f;

    int ntiles = 2 * (qt + 1);        // key tiles of 64 covering [0, qt*128+128)
    for (int t = 0; t < ntiles; t++) {
        int kbase = t * 64;
        __syncthreads();              // previous tile fully consumed
        // Stage K and V tiles: 64 rows x 64 floats each
        for (int i = tid; i < 64 * 16; i += 128) {
            int r = i >> 4;
            int c = (i & 15) * 4;
            const float* src = qkv + ((size_t)(b * SEQ + kbase + r)) * QKV_ROW
                             + DMODEL + h * HD + c;
            *(float4*)&Ks[r][c] = *(const float4*)src;
            *(float4*)&Vs[r][c] = *(const float4*)(src + DMODEL);
        }
        __syncthreads();

        int jmax = qi - kbase + 1;    // causal bound within tile
        if (jmax > 64) jmax = 64;

        for (int j0 = 0; j0 < jmax; j0 += 4) {
            // ---- 4 independent packed dot products, 2 acc-pairs each ----
            float s[4];
            #pragma unroll
            for (int jj = 0; jj < 4; jj++) {
                const float* kr = Ks[j0 + jj];
                ull a0 = 0ull, a1 = 0ull;
                #pragma unroll
                for (int d = 0; d < HD; d += 8) {
                    float4 k0 = *(const float4*)&kr[d];
                    float4 k1 = *(const float4*)&kr[d + 4];
                    a0 = f2_fma(qp[d/2 + 0], f2_pack(k0.x, k0.y), a0);
                    a0 = f2_fma(qp[d/2 + 1], f2_pack(k0.z, k0.w), a0);
                    a1 = f2_fma(qp[d/2 + 2], f2_pack(k1.x, k1.y), a1);
                    a1 = f2_fma(qp[d/2 + 3], f2_pack(k1.z, k1.w), a1);
                }
                float2 r = f2_unpack(f2_add(a0, a1));
                float sv = (r.x + r.y) * 0.125f;
                // causal mask within chunk (p becomes exp(-inf)=0)
                s[jj] = (j0 + jj < jmax) ? sv : -INFINITY;
            }

            // ---- branch-free online softmax update ----
            float mn = fmaxf(fmaxf(fmaxf(s[0], s[1]), fmaxf(s[2], s[3])), m);
            float corr = __expf(m - mn);   // ==1 if max unchanged; ==0 from -inf start
            m = mn;
            float p0 = __expf(s[0] - m);
            float p1 = __expf(s[1] - m);
            float p2 = __expf(s[2] - m);
            float p3 = __expf(s[3] - m);
            l = fmaf(l, corr, (p0 + p1) + (p2 + p3));

            ull pp0 = f2_pack(p0, p0);
            ull pp1 = f2_pack(p1, p1);
            ull pp2 = f2_pack(p2, p2);
            ull pp3 = f2_pack(p3, p3);
            ull cc  = f2_pack(corr, corr);

            #pragma unroll
            for (int d = 0; d < HD; d += 4) {
                int i = d / 2;
                float4 v0 = *(const float4*)&Vs[j0 + 0][d];
                float4 v1 = *(const float4*)&Vs[j0 + 1][d];
                float4 v2 = *(const float4*)&Vs[j0 + 2][d];
                float4 v3 = *(const float4*)&Vs[j0 + 3][d];
                ull t0 = f2_mul(op[i + 0], cc);
                ull t1 = f2_mul(op[i + 1], cc);
                t0 = f2_fma(pp0, f2_pack(v0.x, v0.y), t0);
                t1 = f2_fma(pp0, f2_pack(v0.z, v0.w), t1);
                t0 = f2_fma(pp1, f2_pack(v1.x, v1.y), t0);
                t1 = f2_fma(pp1, f2_pack(v1.z, v1.w), t1);
                t0 = f2_fma(pp2, f2_pack(v2.x, v2.y), t0);
                t1 = f2_fma(pp2, f2_pack(v2.z, v2.w), t1);
                t0 = f2_fma(pp3, f2_pack(v3.x, v3.y), t0);
                t1 = f2_fma(pp3, f2_pack(v3.z, v3.w), t1);
                op[i + 0] = t0;
                op[i + 1] = t1;
            }
        }
    }

    float inv = 1.f / l;
    float* orow = out + ((size_t)(b * SEQ + qi)) * DMODEL + h * HD;
    #pragma unroll
    for (int d = 0; d < HD; d += 4) {
        float2 p0 = f2_unpack(op[d/2 + 0]);
        float2 p1 = f2_unpack(op[d/2 + 1]);
        float4 v;
        v.x = p0.x * inv; v.y = p0.y * inv;
        v.z = p1.x * inv; v.w = p1.y * inv;
        *(float4*)&orow[d] = v;
    }
}

// ---------------------------------------------------------------------------
// Launch
// ---------------------------------------------------------------------------
extern "C" void kernel_launch(void* const* d_in, const int* in_sizes, int n_in,
                              void* d_out, int out_size)
{
    const float* hidden = (const float*)d_in[0];   // [B,S,D]
    const float* W_attn = (const float*)d_in[1];   // [D,3D]
    const float* b_attn = (const float*)d_in[2];   // [3D]
    const float* W_proj = (const float*)d_in[3];   // [D,D]
    const float* b_proj = (const float*)d_in[4];   // [D]
    float* out = (float*)d_out;                    // [B,S,D]

    float* qkv = nullptr;
    float* att = nullptr;
    cudaGetSymbolAddress((void**)&qkv, g_qkv);
    cudaGetSymbolAddress((void**)&att, g_att);

    const int M = BATCH * SEQ;   // 4096

    // 1) QKV projection: [4096,1024] @ [1024,3072] + b
    {
        dim3 grid(3 * DMODEL / 128, M / 128);  // (24, 32)
        gemm_bias_kernel<<<grid, 256>>>(hidden, W_attn, b_attn, qkv,
                                        M, 3 * DMODEL, DMODEL);
    }
    // 2) Causal attention
    {
        dim3 grid(SEQ / 128, NHEAD, BATCH);    // (16, 16, 2)
        attn_kernel<<<grid, 128>>>(qkv, att);
    }
    // 3) Output projection: [4096,1024] @ [1024,1024] + b
    {
        dim3 grid(DMODEL / 128, M / 128);      // (8, 32)
        gemm_bias_kernel<<<grid, 256>>>(att, W_proj, b_proj, out,
                                        M, DMODEL, DMODEL);
    }
}

// round 7
// speedup vs baseline: 1.7033x; 1.3164x over previous
#include <cuda_runtime.h>
#include <cuda_bf16.h>
#include <math.h>

// Problem constants (fixed by the reference)
#define BATCH 2
#define SEQ   2048
#define DMODEL 1024
#define NHEAD 16
#define HD    64          // head dim
#define QKV_ROW (3*DMODEL)

typedef unsigned long long ull;
typedef unsigned int uint32;

// ---- packed f32x2 helpers (sm_103a) ---------------------------------------
__device__ __forceinline__ ull f2_fma(ull a, ull b, ull c) {
    ull d;
    asm("fma.rn.f32x2 %0, %1, %2, %3;" : "=l"(d) : "l"(a), "l"(b), "l"(c));
    return d;
}
__device__ __forceinline__ ull f2_mul(ull a, ull b) {
    ull d;
    asm("mul.rn.f32x2 %0, %1, %2;" : "=l"(d) : "l"(a), "l"(b));
    return d;
}
__device__ __forceinline__ ull f2_add(ull a, ull b) {
    ull d;
    asm("add.rn.f32x2 %0, %1, %2;" : "=l"(d) : "l"(a), "l"(b));
    return d;
}
__device__ __forceinline__ ull f2_pack(float lo, float hi) {
    ull d;
    asm("mov.b64 %0, {%1, %2};" : "=l"(d) : "f"(lo), "f"(hi));
    return d;
}
__device__ __forceinline__ float2 f2_unpack(ull v) {
    float lo, hi;
    asm("mov.b64 {%0, %1}, %2;" : "=f"(lo), "=f"(hi) : "l"(v));
    return make_float2(lo, hi);
}

// ---- mma / ldmatrix wrappers ----------------------------------------------
__device__ __forceinline__ void ldsm_x4(uint32 r[4], uint32 addr) {
    asm volatile("ldmatrix.sync.aligned.m8n8.x4.shared.b16 {%0,%1,%2,%3}, [%4];"
                 : "=r"(r[0]), "=r"(r[1]), "=r"(r[2]), "=r"(r[3]) : "r"(addr));
}
__device__ __forceinline__ void ldsm_x4_t(uint32 r[4], uint32 addr) {
    asm volatile("ldmatrix.sync.aligned.m8n8.x4.trans.shared.b16 {%0,%1,%2,%3}, [%4];"
                 : "=r"(r[0]), "=r"(r[1]), "=r"(r[2]), "=r"(r[3]) : "r"(addr));
}
__device__ __forceinline__ void mma_bf16(float d[4], const uint32 a[4],
                                         uint32 b0, uint32 b1) {
    asm volatile(
        "mma.sync.aligned.m16n8k16.row.col.f32.bf16.bf16.f32 "
        "{%0,%1,%2,%3}, {%4,%5,%6,%7}, {%8,%9}, {%10,%11,%12,%13};"
        : "=f"(d[0]), "=f"(d[1]), "=f"(d[2]), "=f"(d[3])
        : "r"(a[0]), "r"(a[1]), "r"(a[2]), "r"(a[3]),
          "r"(b0), "r"(b1),
          "f"(d[0]), "f"(d[1]), "f"(d[2]), "f"(d[3]));
}

// Scratch (allocation-free rule: __device__ globals)
__device__ float g_qkv[(size_t)BATCH*SEQ*QKV_ROW];        // [B,S,3D] fp32
__device__ float g_att[(size_t)BATCH*SEQ*DMODEL];         // [B,S,D] fp32
__device__ __nv_bfloat16 g_hid_h[(size_t)BATCH*SEQ*DMODEL];
__device__ __nv_bfloat16 g_hid_l[(size_t)BATCH*SEQ*DMODEL];
__device__ __nv_bfloat16 g_wa_h[(size_t)DMODEL*3*DMODEL];
__device__ __nv_bfloat16 g_wa_l[(size_t)DMODEL*3*DMODEL];
__device__ __nv_bfloat16 g_wp_h[(size_t)DMODEL*DMODEL];
__device__ __nv_bfloat16 g_wp_l[(size_t)DMODEL*DMODEL];
__device__ __nv_bfloat16 g_at_h[(size_t)BATCH*SEQ*DMODEL];
__device__ __nv_bfloat16 g_at_l[(size_t)BATCH*SEQ*DMODEL];

// ---------------------------------------------------------------------------
// fp32 -> (bf16 hi, bf16 lo) split.  hi = bf16(x), lo = bf16(x - hi).
// ---------------------------------------------------------------------------
__global__ __launch_bounds__(256)
void split_kernel(const float* __restrict__ x,
                  __nv_bfloat16* __restrict__ hi,
                  __nv_bfloat16* __restrict__ lo, int n)
{
    int i = (blockIdx.x * 256 + threadIdx.x) * 4;
    if (i >= n) return;
    float4 v = *(const float4*)&x[i];
    __nv_bfloat16 h0 = __float2bfloat16(v.x);
    __nv_bfloat16 h1 = __float2bfloat16(v.y);
    __nv_bfloat16 h2 = __float2bfloat16(v.z);
    __nv_bfloat16 h3 = __float2bfloat16(v.w);
    __nv_bfloat16 l0 = __float2bfloat16(v.x - __bfloat162float(h0));
    __nv_bfloat16 l1 = __float2bfloat16(v.y - __bfloat162float(h1));
    __nv_bfloat16 l2 = __float2bfloat16(v.z - __bfloat162float(h2));
    __nv_bfloat16 l3 = __float2bfloat16(v.w - __bfloat162float(h3));
    __nv_bfloat162 hp0 = __nv_bfloat162(h0, h1), hp1 = __nv_bfloat162(h2, h3);
    __nv_bfloat162 lp0 = __nv_bfloat162(l0, l1), lp1 = __nv_bfloat162(l2, l3);
    *(__nv_bfloat162*)&hi[i]     = hp0;
    *(__nv_bfloat162*)&hi[i + 2] = hp1;
    *(__nv_bfloat162*)&lo[i]     = lp0;
    *(__nv_bfloat162*)&lo[i + 2] = lp1;
}

// ---------------------------------------------------------------------------
// Tensor-core GEMM with bias (bf16 3-term split, fp32 accumulate):
//   C[M,N] = (Ah+Al)[M,K] @ (Wh+Wl)[K,N] + bias   (dropping Al*Wl)
// BM=128, BN=128, BK=32, 256 threads / 8 warps (4m x 2n), warp tile 32x64.
// A smem: row-major, padded row stride 5 chunks (80B) -> conflict-free ldsm.
// W smem: row-major [k][n], padded row stride 17 chunks (272B) -> conflict-free
//         ldmatrix.trans.
// ---------------------------------------------------------------------------
__global__ __launch_bounds__(256, 1)
void gemm_mma_kernel(const __nv_bfloat16* __restrict__ Ah,
                     const __nv_bfloat16* __restrict__ Al,
                     const __nv_bfloat16* __restrict__ Wh,
                     const __nv_bfloat16* __restrict__ Wl,
                     const float* __restrict__ bias,
                     float* __restrict__ C,
                     int M, int N, int K)
{
    // smem as 16B chunks
    __shared__ uint4 sAh[128 * 5];   // 128 rows, 4 data chunks + 1 pad
    __shared__ uint4 sAl[128 * 5];
    __shared__ uint4 sWh[32 * 17];   // 32 k-rows, 16 data chunks + 1 pad
    __shared__ uint4 sWl[32 * 17];

    const int tid  = threadIdx.x;
    const int lane = tid & 31;
    const int wid  = tid >> 5;
    const int warp_m = wid & 3;          // 0..3 -> 32-row slices
    const int warp_n = wid >> 2;         // 0..1 -> 64-col slices
    const int row0 = blockIdx.y * 128;
    const int col0 = blockIdx.x * 128;

    // ldmatrix lane address components
    const int j  = lane & 7;
    const int q  = lane >> 3;
    const int a_row_off = j + (q & 1) * 8;     // row within atom
    const int a_chk_off = q >> 1;              // k-chunk within atom
    // A base addrs (ks=0) for the 2 m-atoms, hi & lo
    uint32 aBh[2], aBl[2];
    uint32 sAh_b = (uint32)__cvta_generic_to_shared(sAh);
    uint32 sAl_b = (uint32)__cvta_generic_to_shared(sAl);
    uint32 sWh_b = (uint32)__cvta_generic_to_shared(sWh);
    uint32 sWl_b = (uint32)__cvta_generic_to_shared(sWl);
    #pragma unroll
    for (int ma = 0; ma < 2; ma++) {
        int r = warp_m * 32 + ma * 16 + a_row_off;
        aBh[ma] = sAh_b + (uint32)(r * 5 + a_chk_off) * 16;
        aBl[ma] = sAl_b + (uint32)(r * 5 + a_chk_off) * 16;
    }
    // W base addrs (ks=0) for the 4 n-atom pairs, hi & lo
    uint32 wBh[4], wBl[4];
    #pragma unroll
    for (int nb = 0; nb < 4; nb++) {
        int k = j + (q & 1) * 8;
        int chk = (warp_n * 64 + nb * 16) / 8 + (q >> 1);
        wBh[nb] = sWh_b + (uint32)(k * 17 + chk) * 16;
        wBl[nb] = sWl_b + (uint32)(k * 17 + chk) * 16;
    }

    float acc[2][8][4];
    #pragma unroll
    for (int ma = 0; ma < 2; ma++)
        #pragma unroll
        for (int na = 0; na < 8; na++)
            #pragma unroll
            for (int i = 0; i < 4; i++)
                acc[ma][na][i] = 0.f;

    for (int k0 = 0; k0 < K; k0 += 32) {
        // ---- load A tiles: 512 chunks each (hi, lo); 2 per thread ----
        #pragma unroll
        for (int t = 0; t < 2; t++) {
            int id  = tid + t * 256;           // 0..511
            int r   = id >> 2;                 // 0..127
            int c   = id & 3;                  // 0..3
            size_t g = (size_t)(row0 + r) * K + k0 + c * 8;
            sAh[r * 5 + c] = *(const uint4*)&Ah[g];
            sAl[r * 5 + c] = *(const uint4*)&Al[g];
        }
        // ---- load W tiles: 512 chunks each; 2 per thread ----
        #pragma unroll
        for (int t = 0; t < 2; t++) {
            int id  = tid + t * 256;
            int r   = id >> 4;                 // 0..31 (k)
            int c   = id & 15;                 // 0..15 (n-chunk)
            size_t g = (size_t)(k0 + r) * N + col0 + c * 8;
            sWh[r * 17 + c] = *(const uint4*)&Wh[g];
            sWl[r * 17 + c] = *(const uint4*)&Wl[g];
        }
        __syncthreads();

        #pragma unroll
        for (int ks = 0; ks < 2; ks++) {
            uint32 ah[2][4], al[2][4];
            ldsm_x4(ah[0], aBh[0] + ks * 32);
            ldsm_x4(ah[1], aBh[1] + ks * 32);
            ldsm_x4(al[0], aBl[0] + ks * 32);
            ldsm_x4(al[1], aBl[1] + ks * 32);

            #pragma unroll
            for (int nb = 0; nb < 4; nb++) {
                uint32 bh[4], bl[4];
                ldsm_x4_t(bh, wBh[nb] + ks * 4352);   // +16 k-rows * 272B
                ldsm_x4_t(bl, wBl[nb] + ks * 4352);
                #pragma unroll
                for (int ma = 0; ma < 2; ma++) {
                    mma_bf16(acc[ma][2*nb],   ah[ma], bh[0], bh[1]);
                    mma_bf16(acc[ma][2*nb],   ah[ma], bl[0], bl[1]);
                    mma_bf16(acc[ma][2*nb],   al[ma], bh[0], bh[1]);
                    mma_bf16(acc[ma][2*nb+1], ah[ma], bh[2], bh[3]);
                    mma_bf16(acc[ma][2*nb+1], ah[ma], bl[2], bl[3]);
                    mma_bf16(acc[ma][2*nb+1], al[ma], bh[2], bh[3]);
                }
            }
        }
        __syncthreads();
    }

    // ---- epilogue: bias + store ----
    int r_base = row0 + warp_m * 32 + (lane >> 2);
    int c_base = col0 + warp_n * 64 + (lane & 3) * 2;
    float2 bv[8];
    #pragma unroll
    for (int na = 0; na < 8; na++) {
        int c = c_base + na * 8;
        bv[na] = make_float2(bias[c], bias[c + 1]);
    }
    #pragma unroll
    for (int ma = 0; ma < 2; ma++) {
        int r = r_base + ma * 16;
        #pragma unroll
        for (int na = 0; na < 8; na++) {
            int c = c_base + na * 8;
            float2 o0 = make_float2(acc[ma][na][0] + bv[na].x,
                                    acc[ma][na][1] + bv[na].y);
            float2 o1 = make_float2(acc[ma][na][2] + bv[na].x,
                                    acc[ma][na][3] + bv[na].y);
            *(float2*)&C[(size_t)r * N + c]       = o0;
            *(float2*)&C[(size_t)(r + 8) * N + c] = o1;
        }
    }
}

// ---------------------------------------------------------------------------
// Causal flash attention, fp32, f32x2 packed math (unchanged from R6).
// ---------------------------------------------------------------------------
__global__ __launch_bounds__(128, 3)
void attn_kernel(const float* __restrict__ qkv, float* __restrict__ out)
{
    int qt = (int)gridDim.x - 1 - (int)blockIdx.x;
    int h  = blockIdx.y;
    int b  = blockIdx.z;
    int tid = threadIdx.x;
    int qi = qt * 128 + tid;

    __shared__ float Ks[64][HD];
    __shared__ float Vs[64][HD];

    const float* qrow = qkv + ((size_t)(b * SEQ + qi)) * QKV_ROW + h * HD;
    ull qp[HD/2], op[HD/2];
    #pragma unroll
    for (int d = 0; d < HD; d += 4) {
        float4 v = *(const float4*)&qrow[d];
        qp[d/2 + 0] = f2_pack(v.x, v.y);
        qp[d/2 + 1] = f2_pack(v.z, v.w);
    }
    #pragma unroll
    for (int i = 0; i < HD/2; i++) op[i] = 0ull;

    float m = -INFINITY;
    float l = 0.f;

    int ntiles = 2 * (qt + 1);
    for (int t = 0; t < ntiles; t++) {
        int kbase = t * 64;
        __syncthreads();
        for (int i = tid; i < 64 * 16; i += 128) {
            int r = i >> 4;
            int c = (i & 15) * 4;
            const float* src = qkv + ((size_t)(b * SEQ + kbase + r)) * QKV_ROW
                             + DMODEL + h * HD + c;
            *(float4*)&Ks[r][c] = *(const float4*)src;
            *(float4*)&Vs[r][c] = *(const float4*)(src + DMODEL);
        }
        __syncthreads();

        int jmax = qi - kbase + 1;
        if (jmax > 64) jmax = 64;

        for (int j0 = 0; j0 < jmax; j0 += 4) {
            float s[4];
            #pragma unroll
            for (int jj = 0; jj < 4; jj++) {
                const float* kr = Ks[j0 + jj];
                ull a0 = 0ull, a1 = 0ull;
                #pragma unroll
                for (int d = 0; d < HD; d += 8) {
                    float4 k0 = *(const float4*)&kr[d];
                    float4 k1 = *(const float4*)&kr[d + 4];
                    a0 = f2_fma(qp[d/2 + 0], f2_pack(k0.x, k0.y), a0);
                    a0 = f2_fma(qp[d/2 + 1], f2_pack(k0.z, k0.w), a0);
                    a1 = f2_fma(qp[d/2 + 2], f2_pack(k1.x, k1.y), a1);
                    a1 = f2_fma(qp[d/2 + 3], f2_pack(k1.z, k1.w), a1);
                }
                float2 r = f2_unpack(f2_add(a0, a1));
                float sv = (r.x + r.y) * 0.125f;
                s[jj] = (j0 + jj < jmax) ? sv : -INFINITY;
            }

            float mn = fmaxf(fmaxf(fmaxf(s[0], s[1]), fmaxf(s[2], s[3])), m);
            float corr = __expf(m - mn);
            m = mn;
            float p0 = __expf(s[0] - m);
            float p1 = __expf(s[1] - m);
            float p2 = __expf(s[2] - m);
            float p3 = __expf(s[3] - m);
            l = fmaf(l, corr, (p0 + p1) + (p2 + p3));

            ull pp0 = f2_pack(p0, p0);
            ull pp1 = f2_pack(p1, p1);
            ull pp2 = f2_pack(p2, p2);
            ull pp3 = f2_pack(p3, p3);
            ull cc  = f2_pack(corr, corr);

            #pragma unroll
            for (int d = 0; d < HD; d += 4) {
                int i = d / 2;
                float4 v0 = *(const float4*)&Vs[j0 + 0][d];
                float4 v1 = *(const float4*)&Vs[j0 + 1][d];
                float4 v2 = *(const float4*)&Vs[j0 + 2][d];
                float4 v3 = *(const float4*)&Vs[j0 + 3][d];
                ull t0 = f2_mul(op[i + 0], cc);
                ull t1 = f2_mul(op[i + 1], cc);
                t0 = f2_fma(pp0, f2_pack(v0.x, v0.y), t0);
                t1 = f2_fma(pp0, f2_pack(v0.z, v0.w), t1);
                t0 = f2_fma(pp1, f2_pack(v1.x, v1.y), t0);
                t1 = f2_fma(pp1, f2_pack(v1.z, v1.w), t1);
                t0 = f2_fma(pp2, f2_pack(v2.x, v2.y), t0);
                t1 = f2_fma(pp2, f2_pack(v2.z, v2.w), t1);
                t0 = f2_fma(pp3, f2_pack(v3.x, v3.y), t0);
                t1 = f2_fma(pp3, f2_pack(v3.z, v3.w), t1);
                op[i + 0] = t0;
                op[i + 1] = t1;
            }
        }
    }

    float inv = 1.f / l;
    float* orow = out + ((size_t)(b * SEQ + qi)) * DMODEL + h * HD;
    #pragma unroll
    for (int d = 0; d < HD; d += 4) {
        float2 p0 = f2_unpack(op[d/2 + 0]);
        float2 p1 = f2_unpack(op[d/2 + 1]);
        float4 v;
        v.x = p0.x * inv; v.y = p0.y * inv;
        v.z = p1.x * inv; v.w = p1.y * inv;
        *(float4*)&orow[d] = v;
    }
}

// ---------------------------------------------------------------------------
// Launch
// ---------------------------------------------------------------------------
extern "C" void kernel_launch(void* const* d_in, const int* in_sizes, int n_in,
                              void* d_out, int out_size)
{
    const float* hidden = (const float*)d_in[0];   // [B,S,D]
    const float* W_attn = (const float*)d_in[1];   // [D,3D]
    const float* b_attn = (const float*)d_in[2];   // [3D]
    const float* W_proj = (const float*)d_in[3];   // [D,D]
    const float* b_proj = (const float*)d_in[4];   // [D]
    float* out = (float*)d_out;                    // [B,S,D]

    float *qkv, *att;
    __nv_bfloat16 *hid_h, *hid_l, *wa_h, *wa_l, *wp_h, *wp_l, *at_h, *at_l;
    cudaGetSymbolAddress((void**)&qkv, g_qkv);
    cudaGetSymbolAddress((void**)&att, g_att);
    cudaGetSymbolAddress((void**)&hid_h, g_hid_h);
    cudaGetSymbolAddress((void**)&hid_l, g_hid_l);
    cudaGetSymbolAddress((void**)&wa_h, g_wa_h);
    cudaGetSymbolAddress((void**)&wa_l, g_wa_l);
    cudaGetSymbolAddress((void**)&wp_h, g_wp_h);
    cudaGetSymbolAddress((void**)&wp_l, g_wp_l);
    cudaGetSymbolAddress((void**)&at_h, g_at_h);
    cudaGetSymbolAddress((void**)&at_l, g_at_l);

    const int M = BATCH * SEQ;   // 4096

    // 0) fp32 -> bf16 hi/lo splits
    {
        int n1 = M * DMODEL;                  // hidden
        split_kernel<<<n1 / 1024, 256>>>(hidden, hid_h, hid_l, n1);
        int n2 = DMODEL * 3 * DMODEL;         // W_attn
        split_kernel<<<n2 / 1024, 256>>>(W_attn, wa_h, wa_l, n2);
        int n3 = DMODEL * DMODEL;             // W_proj
        split_kernel<<<n3 / 1024, 256>>>(W_proj, wp_h, wp_l, n3);
    }
    // 1) QKV projection (tensor cores): [4096,1024] @ [1024,3072] + b
    {
        dim3 grid(3 * DMODEL / 128, M / 128);  // (24, 32)
        gemm_mma_kernel<<<grid, 256>>>(hid_h, hid_l, wa_h, wa_l, b_attn, qkv,
                                       M, 3 * DMODEL, DMODEL);
    }
    // 2) Causal attention (fp32)
    {
        dim3 grid(SEQ / 128, NHEAD, BATCH);    // (16, 16, 2)
        attn_kernel<<<grid, 128>>>(qkv, att);
    }
    // 3) split attention output, then output projection (tensor cores)
    {
        int n4 = M * DMODEL;
        split_kernel<<<n4 / 1024, 256>>>(att, at_h, at_l, n4);
        dim3 grid(DMODEL / 128, M / 128);      // (8, 32)
        gemm_mma_kernel<<<grid, 256>>>(at_h, at_l, wp_h, wp_l, b_proj, out,
                                       M, DMODEL, DMODEL);
    }
}

// round 8
// speedup vs baseline: 4.0352x; 2.3691x over previous
#include <cuda_runtime.h>
#include <cuda_bf16.h>
#include <math.h>

// Problem constants (fixed by the reference)
#define BATCH 2
#define SEQ   2048
#define DMODEL 1024
#define NHEAD 16
#define HD    64          // head dim
#define QKV_ROW (3*DMODEL)

typedef unsigned long long ull;
typedef unsigned int uint32;

// ---- mma / ldmatrix / cp.async wrappers -----------------------------------
__device__ __forceinline__ void ldsm_x4(uint32 r[4], uint32 addr) {
    asm volatile("ldmatrix.sync.aligned.m8n8.x4.shared.b16 {%0,%1,%2,%3}, [%4];"
                 : "=r"(r[0]), "=r"(r[1]), "=r"(r[2]), "=r"(r[3]) : "r"(addr));
}
__device__ __forceinline__ void ldsm_x4_t(uint32 r[4], uint32 addr) {
    asm volatile("ldmatrix.sync.aligned.m8n8.x4.trans.shared.b16 {%0,%1,%2,%3}, [%4];"
                 : "=r"(r[0]), "=r"(r[1]), "=r"(r[2]), "=r"(r[3]) : "r"(addr));
}
__device__ __forceinline__ void mma_bf16(float d[4], const uint32 a[4],
                                         uint32 b0, uint32 b1) {
    asm volatile(
        "mma.sync.aligned.m16n8k16.row.col.f32.bf16.bf16.f32 "
        "{%0,%1,%2,%3}, {%4,%5,%6,%7}, {%8,%9}, {%10,%11,%12,%13};"
        : "=f"(d[0]), "=f"(d[1]), "=f"(d[2]), "=f"(d[3])
        : "r"(a[0]), "r"(a[1]), "r"(a[2]), "r"(a[3]),
          "r"(b0), "r"(b1),
          "f"(d[0]), "f"(d[1]), "f"(d[2]), "f"(d[3]));
}
__device__ __forceinline__ void cp16(uint32 smem_addr, const void* gptr) {
    asm volatile("cp.async.ca.shared.global [%0], [%1], 16;\n"
                 :: "r"(smem_addr), "l"(gptr));
}
__device__ __forceinline__ void cp_commit() {
    asm volatile("cp.async.commit_group;\n");
}
template<int N> __device__ __forceinline__ void cp_wait() {
    asm volatile("cp.async.wait_group %0;\n" :: "n"(N));
}

// split one float pair -> packed bf16x2 hi + packed bf16x2 lo
__device__ __forceinline__ void split2(float x, float y, uint32 &hi, uint32 &lo) {
    __nv_bfloat162 h2 = __floats2bfloat162_rn(x, y);
    hi = *reinterpret_cast<uint32*>(&h2);
    float rx = x - __bfloat162float(h2.x);
    float ry = y - __bfloat162float(h2.y);
    __nv_bfloat162 l2 = __floats2bfloat162_rn(rx, ry);
    lo = *reinterpret_cast<uint32*>(&l2);
}

// Scratch (allocation-free rule: __device__ globals)
__device__ float g_qkv[(size_t)BATCH*SEQ*QKV_ROW];        // [B,S,3D] fp32
__device__ float g_att[(size_t)BATCH*SEQ*DMODEL];         // [B,S,D] fp32
__device__ __nv_bfloat16 g_hid_h[(size_t)BATCH*SEQ*DMODEL];
__device__ __nv_bfloat16 g_hid_l[(size_t)BATCH*SEQ*DMODEL];
__device__ __nv_bfloat16 g_wa_h[(size_t)DMODEL*3*DMODEL];
__device__ __nv_bfloat16 g_wa_l[(size_t)DMODEL*3*DMODEL];
__device__ __nv_bfloat16 g_wp_h[(size_t)DMODEL*DMODEL];
__device__ __nv_bfloat16 g_wp_l[(size_t)DMODEL*DMODEL];
__device__ __nv_bfloat16 g_at_h[(size_t)BATCH*SEQ*DMODEL];
__device__ __nv_bfloat16 g_at_l[(size_t)BATCH*SEQ*DMODEL];
// head-major [B][H][S][HD] bf16 splits of q (pre-scaled by 1/8), k, v
#define HEADS_ELEMS ((size_t)BATCH*NHEAD*SEQ*HD)
__device__ __nv_bfloat16 g_q_h[HEADS_ELEMS];
__device__ __nv_bfloat16 g_q_l[HEADS_ELEMS];
__device__ __nv_bfloat16 g_k_h[HEADS_ELEMS];
__device__ __nv_bfloat16 g_k_l[HEADS_ELEMS];
__device__ __nv_bfloat16 g_v_h[HEADS_ELEMS];
__device__ __nv_bfloat16 g_v_l[HEADS_ELEMS];

// ---------------------------------------------------------------------------
// fp32 -> (bf16 hi, bf16 lo) split (flat arrays).
// ---------------------------------------------------------------------------
__global__ __launch_bounds__(256)
void split_kernel(const float* __restrict__ x,
                  __nv_bfloat16* __restrict__ hi,
                  __nv_bfloat16* __restrict__ lo, int n)
{
    int i = (blockIdx.x * 256 + threadIdx.x) * 4;
    if (i >= n) return;
    float4 v = *(const float4*)&x[i];
    uint32 h0, l0, h1, l1;
    split2(v.x, v.y, h0, l0);
    split2(v.z, v.w, h1, l1);
    *(uint32*)&hi[i]     = h0;
    *(uint32*)&hi[i + 2] = h1;
    *(uint32*)&lo[i]     = l0;
    *(uint32*)&lo[i + 2] = l1;
}

// ---------------------------------------------------------------------------
// g_qkv [B,S,3D] fp32 -> head-major bf16 hi/lo arrays [B][H][S][HD].
// Q pre-scaled by 0.125 (exact power of two) before splitting.
// One thread handles 4 d-elements of q,k,v for one (b,s,h).
// ---------------------------------------------------------------------------
__global__ __launch_bounds__(256)
void split_qkv_kernel(const float* __restrict__ qkv,
                      __nv_bfloat16* __restrict__ Qh, __nv_bfloat16* __restrict__ Ql,
                      __nv_bfloat16* __restrict__ Kh, __nv_bfloat16* __restrict__ Kl,
                      __nv_bfloat16* __restrict__ Vh, __nv_bfloat16* __restrict__ Vl)
{
    int idx = blockIdx.x * 256 + threadIdx.x;     // 20 bits total
    int c = idx & 15;                // d-chunk of 4
    int h = (idx >> 4) & 15;
    int s = (idx >> 8) & 2047;
    int b = idx >> 19;
    const float* base = qkv + ((size_t)(b * SEQ + s)) * QKV_ROW;
    size_t oi = (((size_t)(b * NHEAD + h)) * SEQ + s) * HD + c * 4;

    float4 q4 = *(const float4*)&base[h * HD + c * 4];
    q4.x *= 0.125f; q4.y *= 0.125f; q4.z *= 0.125f; q4.w *= 0.125f;
    uint32 h0, l0, h1, l1;
    split2(q4.x, q4.y, h0, l0); split2(q4.z, q4.w, h1, l1);
    *(uint32*)&Qh[oi] = h0; *(uint32*)&Qh[oi + 2] = h1;
    *(uint32*)&Ql[oi] = l0; *(uint32*)&Ql[oi + 2] = l1;

    float4 k4 = *(const float4*)&base[DMODEL + h * HD + c * 4];
    split2(k4.x, k4.y, h0, l0); split2(k4.z, k4.w, h1, l1);
    *(uint32*)&Kh[oi] = h0; *(uint32*)&Kh[oi + 2] = h1;
    *(uint32*)&Kl[oi] = l0; *(uint32*)&Kl[oi + 2] = l1;

    float4 v4 = *(const float4*)&base[2 * DMODEL + h * HD + c * 4];
    split2(v4.x, v4.y, h0, l0); split2(v4.z, v4.w, h1, l1);
    *(uint32*)&Vh[oi] = h0; *(uint32*)&Vh[oi + 2] = h1;
    *(uint32*)&Vl[oi] = l0; *(uint32*)&Vl[oi + 2] = l1;
}

// ---------------------------------------------------------------------------
// Tensor-core GEMM with bias (bf16 3-term split, fp32 accumulate),
// cp.async 2-stage double buffered.
//   C[M,N] = (Ah+Al)[M,K] @ (Wh+Wl)[K,N] + bias   (dropping Al*Wl)
// BM=128, BN=128, BK=32, 256 threads / 8 warps (4m x 2n), warp tile 32x64.
// Dynamic smem chunk map (uint4 units):
//   sAh [2][640] @0, sAl [2][640] @1280, sWh [2][544] @2560, sWl [2][544] @3648
// ---------------------------------------------------------------------------
#define GEMM_SMEM_BYTES (4736 * 16)
__global__ __launch_bounds__(256, 1)
void gemm_mma_kernel(const __nv_bfloat16* __restrict__ Ah,
                     const __nv_bfloat16* __restrict__ Al,
                     const __nv_bfloat16* __restrict__ Wh,
                     const __nv_bfloat16* __restrict__ Wl,
                     const float* __restrict__ bias,
                     float* __restrict__ C,
                     int M, int N, int K)
{
    extern __shared__ uint4 dsm[];
    uint32 base = (uint32)__cvta_generic_to_shared(dsm);
    const uint32 oAh = 0, oAl = 20480, oWh = 40960, oWl = 58368;
    const uint32 stA = 10240, stW = 8704;   // per-stage byte strides

    const int tid  = threadIdx.x;
    const int lane = tid & 31;
    const int wid  = tid >> 5;
    const int warp_m = wid & 3;
    const int warp_n = wid >> 2;
    const int row0 = blockIdx.y * 128;
    const int col0 = blockIdx.x * 128;

    // ldmatrix lane offsets
    const int j  = lane & 7;
    const int q  = lane >> 3;
    const int a_row_off = j + (q & 1) * 8;
    const int a_chk_off = q >> 1;
    uint32 aOff[2];
    #pragma unroll
    for (int ma = 0; ma < 2; ma++) {
        int r = warp_m * 32 + ma * 16 + a_row_off;
        aOff[ma] = (uint32)(r * 5 + a_chk_off) * 16;
    }
    uint32 wOff[4];
    #pragma unroll
    for (int nb = 0; nb < 4; nb++) {
        int k = j + (q & 1) * 8;
        int chk = (warp_n * 64 + nb * 16) / 8 + (q >> 1);
        wOff[nb] = (uint32)(k * 17 + chk) * 16;
    }

    // loader coordinates
    int aR[2], aC[2], wR[2], wC[2];
    #pragma unroll
    for (int t = 0; t < 2; t++) {
        int id = tid + t * 256;
        aR[t] = id >> 2;  aC[t] = id & 3;
        wR[t] = id >> 4;  wC[t] = id & 15;
    }

    float acc[2][8][4];
    #pragma unroll
    for (int ma = 0; ma < 2; ma++)
        #pragma unroll
        for (int na = 0; na < 8; na++)
            #pragma unroll
            for (int i = 0; i < 4; i++)
                acc[ma][na][i] = 0.f;

    const int nkt = K / 32;
    // prologue: stage 0
    #pragma unroll
    for (int t = 0; t < 2; t++) {
        cp16(base + oAh + (uint32)(aR[t] * 5 + aC[t]) * 16,
             &Ah[(size_t)(row0 + aR[t]) * K + aC[t] * 8]);
        cp16(base + oAl + (uint32)(aR[t] * 5 + aC[t]) * 16,
             &Al[(size_t)(row0 + aR[t]) * K + aC[t] * 8]);
        cp16(base + oWh + (uint32)(wR[t] * 17 + wC[t]) * 16,
             &Wh[(size_t)(wR[t]) * N + col0 + wC[t] * 8]);
        cp16(base + oWl + (uint32)(wR[t] * 17 + wC[t]) * 16,
             &Wl[(size_t)(wR[t]) * N + col0 + wC[t] * 8]);
    }
    cp_commit();

    for (int kt = 0; kt < nkt; kt++) {
        if (kt + 1 < nkt) {
            uint32 st = (uint32)((kt + 1) & 1);
            int k0n = (kt + 1) * 32;
            #pragma unroll
            for (int t = 0; t < 2; t++) {
                cp16(base + oAh + st * stA + (uint32)(aR[t] * 5 + aC[t]) * 16,
                     &Ah[(size_t)(row0 + aR[t]) * K + k0n + aC[t] * 8]);
                cp16(base + oAl + st * stA + (uint32)(aR[t] * 5 + aC[t]) * 16,
                     &Al[(size_t)(row0 + aR[t]) * K + k0n + aC[t] * 8]);
                cp16(base + oWh + st * stW + (uint32)(wR[t] * 17 + wC[t]) * 16,
                     &Wh[(size_t)(k0n + wR[t]) * N + col0 + wC[t] * 8]);
                cp16(base + oWl + st * stW + (uint32)(wR[t] * 17 + wC[t]) * 16,
                     &Wl[(size_t)(k0n + wR[t]) * N + col0 + wC[t] * 8]);
            }
            cp_commit();
            cp_wait<1>();
        } else {
            cp_wait<0>();
        }
        __syncthreads();

        uint32 st = (uint32)(kt & 1);
        uint32 bAh = base + oAh + st * stA;
        uint32 bAl = base + oAl + st * stA;
        uint32 bWh = base + oWh + st * stW;
        uint32 bWl = base + oWl + st * stW;

        #pragma unroll
        for (int ks = 0; ks < 2; ks++) {
            uint32 ah[2][4], al[2][4];
            ldsm_x4(ah[0], bAh + aOff[0] + ks * 32);
            ldsm_x4(ah[1], bAh + aOff[1] + ks * 32);
            ldsm_x4(al[0], bAl + aOff[0] + ks * 32);
            ldsm_x4(al[1], bAl + aOff[1] + ks * 32);
            #pragma unroll
            for (int nb = 0; nb < 4; nb++) {
                uint32 bh[4], bl[4];
                ldsm_x4_t(bh, bWh + wOff[nb] + ks * 4352);   // +16 k-rows * 272B
                ldsm_x4_t(bl, bWl + wOff[nb] + ks * 4352);
                #pragma unroll
                for (int ma = 0; ma < 2; ma++) {
                    mma_bf16(acc[ma][2*nb],   ah[ma], bh[0], bh[1]);
                    mma_bf16(acc[ma][2*nb],   ah[ma], bl[0], bl[1]);
                    mma_bf16(acc[ma][2*nb],   al[ma], bh[0], bh[1]);
                    mma_bf16(acc[ma][2*nb+1], ah[ma], bh[2], bh[3]);
                    mma_bf16(acc[ma][2*nb+1], ah[ma], bl[2], bl[3]);
                    mma_bf16(acc[ma][2*nb+1], al[ma], bh[2], bh[3]);
                }
            }
        }
        __syncthreads();
    }

    // ---- epilogue: bias + store ----
    int r_base = row0 + warp_m * 32 + (lane >> 2);
    int c_base = col0 + warp_n * 64 + (lane & 3) * 2;
    #pragma unroll
    for (int ma = 0; ma < 2; ma++) {
        int r = r_base + ma * 16;
        #pragma unroll
        for (int na = 0; na < 8; na++) {
            int c = c_base + na * 8;
            float bx = bias[c], by = bias[c + 1];
            float2 o0 = make_float2(acc[ma][na][0] + bx, acc[ma][na][1] + by);
            float2 o1 = make_float2(acc[ma][na][2] + bx, acc[ma][na][3] + by);
            *(float2*)&C[(size_t)r * N + c]       = o0;
            *(float2*)&C[(size_t)(r + 8) * N + c] = o1;
        }
    }
}

// ---------------------------------------------------------------------------
// MMA causal flash attention (bf16 3-term splits, fp32 softmax/accum).
// BM=128 q rows/block, BN=64 keys/tile, 8 warps (warp = 16 q rows).
// K/V tiles cp.async double-buffered in dynamic smem:
//   per stage: Kh[64][72] Kl Vh Vl bf16 (72 = 64 data + 8 pad; row=144B=9 chunks)
//   stage stride 36864 B, arrays at +0, +9216, +18432, +27648.
// grid = (S/128, NHEAD, BATCH) with qt reversed for load balance.
// ---------------------------------------------------------------------------
#define ATTN_SMEM_BYTES (2 * 36864)
__global__ __launch_bounds__(256, 1)
void attn_mma_kernel(const __nv_bfloat16* __restrict__ Qh,
                     const __nv_bfloat16* __restrict__ Ql,
                     const __nv_bfloat16* __restrict__ Kh,
                     const __nv_bfloat16* __restrict__ Kl,
                     const __nv_bfloat16* __restrict__ Vh,
                     const __nv_bfloat16* __restrict__ Vl,
                     float* __restrict__ out)
{
    extern __shared__ uint4 dsm[];
    uint32 smem_u = (uint32)__cvta_generic_to_shared(dsm);

    const int tid  = threadIdx.x;
    const int lane = tid & 31;
    const int wq   = tid >> 5;
    const int qt = (int)gridDim.x - 1 - (int)blockIdx.x;
    const int h = blockIdx.y, b = blockIdx.z;
    const int q0 = qt * 128;
    const size_t headoff = ((size_t)(b * NHEAD + h)) * SEQ * HD;

    const int gid = lane >> 2;           // 0..7
    const int tig = lane & 3;            // 0..3
    const int row0 = q0 + wq * 16 + gid; // absolute q row (c0/c1); row1 = row0+8

    // ---- Q fragments straight from global (bf16x2 = uint32 loads) ----
    uint32 qh[4][4], ql[4][4];
    {
        const __nv_bfloat16* Qhb = Qh + headoff;
        const __nv_bfloat16* Qlb = Ql + headoff;
        #pragma unroll
        for (int ks = 0; ks < 4; ks++) {
            int kc = ks * 16 + 2 * tig;
            qh[ks][0] = *(const uint32*)&Qhb[(size_t)row0 * HD + kc];
            qh[ks][1] = *(const uint32*)&Qhb[(size_t)(row0 + 8) * HD + kc];
            qh[ks][2] = *(const uint32*)&Qhb[(size_t)row0 * HD + kc + 8];
            qh[ks][3] = *(const uint32*)&Qhb[(size_t)(row0 + 8) * HD + kc + 8];
            ql[ks][0] = *(const uint32*)&Qlb[(size_t)row0 * HD + kc];
            ql[ks][1] = *(const uint32*)&Qlb[(size_t)(row0 + 8) * HD + kc];
            ql[ks][2] = *(const uint32*)&Qlb[(size_t)row0 * HD + kc + 8];
            ql[ks][3] = *(const uint32*)&Qlb[(size_t)(row0 + 8) * HD + kc + 8];
        }
    }

    // ldmatrix lane-invariant offsets
    const uint32 kOffBase = (uint32)((((lane >> 4) << 3) + (lane & 7)) * 144
                                     + ((lane >> 3) & 1) * 16);
    const uint32 vOffBase = (uint32)(((lane & 7) + (((lane >> 3) & 1) << 3)) * 144
                                     + (lane >> 4) * 16);

    float o[8][4];
    #pragma unroll
    for (int t = 0; t < 8; t++)
        #pragma unroll
        for (int i = 0; i < 4; i++) o[t][i] = 0.f;
    float m0 = -INFINITY, m1 = -INFINITY, l0 = 0.f, l1 = 0.f;

    const __nv_bfloat16* kvsrc[4] = {Kh + headoff, Kl + headoff,
                                     Vh + headoff, Vl + headoff};
    const int ntiles = 2 * (qt + 1);

    // tile loader: 8 x cp16 per thread
    // (arrays Kh,Kl,Vh,Vl each 64 rows x 8 chunks, row stride 9 chunks)
    {
        #pragma unroll
        for (int t = 0; t < 8; t++) {
            int id = tid + t * 256;
            int arr = id >> 9;
            int r = (id >> 3) & 63;
            int c = id & 7;
            cp16(smem_u + (uint32)(arr * 9216 + r * 144 + c * 16),
                 kvsrc[arr] + (size_t)r * HD + c * 8);
        }
        cp_commit();
    }

    for (int tt = 0; tt < ntiles; tt++) {
        int kb = tt * 64;
        if (tt + 1 < ntiles) {
            uint32 stn = (uint32)((tt + 1) & 1) * 36864;
            int kbn = kb + 64;
            #pragma unroll
            for (int t = 0; t < 8; t++) {
                int id = tid + t * 256;
                int arr = id >> 9;
                int r = (id >> 3) & 63;
                int c = id & 7;
                cp16(smem_u + stn + (uint32)(arr * 9216 + r * 144 + c * 16),
                     kvsrc[arr] + (size_t)(kbn + r) * HD + c * 8);
            }
            cp_commit();
            cp_wait<1>();
        } else {
            cp_wait<0>();
        }
        __syncthreads();

        uint32 stb = smem_u + (uint32)(tt & 1) * 36864;
        uint32 khb = stb, klb = stb + 9216, vhb = stb + 18432, vlb = stb + 27648;

        // ---- S = Q K^T (3-term split), n = keys ----
        float s[8][4];
        #pragma unroll
        for (int t = 0; t < 8; t++)
            #pragma unroll
            for (int i = 0; i < 4; i++) s[t][i] = 0.f;

        #pragma unroll
        for (int ks = 0; ks < 4; ks++)
            #pragma unroll
            for (int g = 0; g < 4; g++) {
                uint32 bh[4], bl[4];
                ldsm_x4(bh, khb + (uint32)(g * 2304 + ks * 32) + kOffBase);
                ldsm_x4(bl, klb + (uint32)(g * 2304 + ks * 32) + kOffBase);
                mma_bf16(s[2*g],   qh[ks], bh[0], bh[1]);
                mma_bf16(s[2*g],   qh[ks], bl[0], bl[1]);
                mma_bf16(s[2*g],   ql[ks], bh[0], bh[1]);
                mma_bf16(s[2*g+1], qh[ks], bh[2], bh[3]);
                mma_bf16(s[2*g+1], qh[ks], bl[2], bl[3]);
                mma_bf16(s[2*g+1], ql[ks], bh[2], bh[3]);
            }

        // ---- causal mask (diagonal tiles only) ----
        if (kb + 63 > q0 + wq * 16) {
            #pragma unroll
            for (int t = 0; t < 8; t++) {
                int key = kb + t * 8 + 2 * tig;
                if (key     > row0)     s[t][0] = -INFINITY;
                if (key + 1 > row0)     s[t][1] = -INFINITY;
                if (key     > row0 + 8) s[t][2] = -INFINITY;
                if (key + 1 > row0 + 8) s[t][3] = -INFINITY;
            }
        }

        // ---- online softmax ----
        float r0 = -INFINITY, r1 = -INFINITY;
        #pragma unroll
        for (int t = 0; t < 8; t++) {
            r0 = fmaxf(r0, fmaxf(s[t][0], s[t][1]));
            r1 = fmaxf(r1, fmaxf(s[t][2], s[t][3]));
        }
        r0 = fmaxf(r0, __shfl_xor_sync(0xffffffffu, r0, 1));
        r0 = fmaxf(r0, __shfl_xor_sync(0xffffffffu, r0, 2));
        r1 = fmaxf(r1, __shfl_xor_sync(0xffffffffu, r1, 1));
        r1 = fmaxf(r1, __shfl_xor_sync(0xffffffffu, r1, 2));
        float mn0 = fmaxf(m0, r0), mn1 = fmaxf(m1, r1);
        float c0 = __expf(m0 - mn0), c1 = __expf(m1 - mn1);
        m0 = mn0; m1 = mn1;
        l0 *= c0;  l1 *= c1;
        #pragma unroll
        for (int t = 0; t < 8; t++) {
            s[t][0] = __expf(s[t][0] - m0);
            s[t][1] = __expf(s[t][1] - m0);
            s[t][2] = __expf(s[t][2] - m1);
            s[t][3] = __expf(s[t][3] - m1);
            l0 += s[t][0] + s[t][1];
            l1 += s[t][2] + s[t][3];
        }
        #pragma unroll
        for (int t = 0; t < 8; t++) {
            o[t][0] *= c0; o[t][1] *= c0;
            o[t][2] *= c1; o[t][3] *= c1;
        }

        // ---- pack P (C-frag == A-frag identity), hi/lo split ----
        uint32 ph[4][4], pl[4][4];
        #pragma unroll
        for (int kk = 0; kk < 4; kk++) {
            split2(s[2*kk][0],   s[2*kk][1],   ph[kk][0], pl[kk][0]);
            split2(s[2*kk][2],   s[2*kk][3],   ph[kk][1], pl[kk][1]);
            split2(s[2*kk+1][0], s[2*kk+1][1], ph[kk][2], pl[kk][2]);
            split2(s[2*kk+1][2], s[2*kk+1][3], ph[kk][3], pl[kk][3]);
        }

        // ---- O += P V (3-term split), n = head dim ----
        #pragma unroll
        for (int kk = 0; kk < 4; kk++)
            #pragma unroll
            for (int g = 0; g < 4; g++) {
                uint32 vh4[4], vl4[4];
                ldsm_x4_t(vh4, vhb + (uint32)(kk * 2304 + g * 32) + vOffBase);
                ldsm_x4_t(vl4, vlb + (uint32)(kk * 2304 + g * 32) + vOffBase);
                mma_bf16(o[2*g],   ph[kk], vh4[0], vh4[1]);
                mma_bf16(o[2*g],   ph[kk], vl4[0], vl4[1]);
                mma_bf16(o[2*g],   pl[kk], vh4[0], vh4[1]);
                mma_bf16(o[2*g+1], ph[kk], vh4[2], vh4[3]);
                mma_bf16(o[2*g+1], ph[kk], vl4[2], vl4[3]);
                mma_bf16(o[2*g+1], pl[kk], vh4[2], vh4[3]);
            }
        __syncthreads();
    }

    // ---- finalize: reduce l across quad, normalize, store ----
    l0 += __shfl_xor_sync(0xffffffffu, l0, 1);
    l0 += __shfl_xor_sync(0xffffffffu, l0, 2);
    l1 += __shfl_xor_sync(0xffffffffu, l1, 1);
    l1 += __shfl_xor_sync(0xffffffffu, l1, 2);
    float i0 = 1.f / l0, i1 = 1.f / l1;
    #pragma unroll
    for (int t = 0; t < 8; t++) {
        int col = h * HD + t * 8 + 2 * tig;
        float2 v0 = make_float2(o[t][0] * i0, o[t][1] * i0);
        float2 v1 = make_float2(o[t][2] * i1, o[t][3] * i1);
        *(float2*)&out[((size_t)(b * SEQ + row0)) * DMODEL + col]     = v0;
        *(float2*)&out[((size_t)(b * SEQ + row0 + 8)) * DMODEL + col] = v1;
    }
}

// ---------------------------------------------------------------------------
// Launch
// ---------------------------------------------------------------------------
extern "C" void kernel_launch(void* const* d_in, const int* in_sizes, int n_in,
                              void* d_out, int out_size)
{
    const float* hidden = (const float*)d_in[0];   // [B,S,D]
    const float* W_attn = (const float*)d_in[1];   // [D,3D]
    const float* b_attn = (const float*)d_in[2];   // [3D]
    const float* W_proj = (const float*)d_in[3];   // [D,D]
    const float* b_proj = (const float*)d_in[4];   // [D]
    float* out = (float*)d_out;                    // [B,S,D]

    float *qkv, *att;
    __nv_bfloat16 *hid_h, *hid_l, *wa_h, *wa_l, *wp_h, *wp_l, *at_h, *at_l;
    __nv_bfloat16 *q_h, *q_l, *k_h, *k_l, *v_h, *v_l;
    cudaGetSymbolAddress((void**)&qkv, g_qkv);
    cudaGetSymbolAddress((void**)&att, g_att);
    cudaGetSymbolAddress((void**)&hid_h, g_hid_h);
    cudaGetSymbolAddress((void**)&hid_l, g_hid_l);
    cudaGetSymbolAddress((void**)&wa_h, g_wa_h);
    cudaGetSymbolAddress((void**)&wa_l, g_wa_l);
    cudaGetSymbolAddress((void**)&wp_h, g_wp_h);
    cudaGetSymbolAddress((void**)&wp_l, g_wp_l);
    cudaGetSymbolAddress((void**)&at_h, g_at_h);
    cudaGetSymbolAddress((void**)&at_l, g_at_l);
    cudaGetSymbolAddress((void**)&q_h, g_q_h);
    cudaGetSymbolAddress((void**)&q_l, g_q_l);
    cudaGetSymbolAddress((void**)&k_h, g_k_h);
    cudaGetSymbolAddress((void**)&k_l, g_k_l);
    cudaGetSymbolAddress((void**)&v_h, g_v_h);
    cudaGetSymbolAddress((void**)&v_l, g_v_l);

    // raise dynamic smem limits (idempotent; not a stream op)
    cudaFuncSetAttribute(gemm_mma_kernel,
                         cudaFuncAttributeMaxDynamicSharedMemorySize,
                         GEMM_SMEM_BYTES);
    cudaFuncSetAttribute(attn_mma_kernel,
                         cudaFuncAttributeMaxDynamicSharedMemorySize,
                         ATTN_SMEM_BYTES);

    const int M = BATCH * SEQ;   // 4096

    // 0) fp32 -> bf16 hi/lo splits of GEMM inputs
    {
        int n1 = M * DMODEL;
        split_kernel<<<n1 / 1024, 256>>>(hidden, hid_h, hid_l, n1);
        int n2 = DMODEL * 3 * DMODEL;
        split_kernel<<<n2 / 1024, 256>>>(W_attn, wa_h, wa_l, n2);
        int n3 = DMODEL * DMODEL;
        split_kernel<<<n3 / 1024, 256>>>(W_proj, wp_h, wp_l, n3);
    }
    // 1) QKV projection (tensor cores)
    {
        dim3 grid(3 * DMODEL / 128, M / 128);  // (24, 32)
        gemm_mma_kernel<<<grid, 256, GEMM_SMEM_BYTES>>>(
            hid_h, hid_l, wa_h, wa_l, b_attn, qkv, M, 3 * DMODEL, DMODEL);
    }
    // 2) split qkv into head-major bf16 hi/lo (Q pre-scaled by 1/8)
    {
        int nthr = BATCH * SEQ * NHEAD * 16;   // 1,048,576
        split_qkv_kernel<<<nthr / 256, 256>>>(qkv, q_h, q_l, k_h, k_l, v_h, v_l);
    }
    // 3) causal attention (tensor cores)
    {
        dim3 grid(SEQ / 128, NHEAD, BATCH);    // (16, 16, 2)
        attn_mma_kernel<<<grid, 256, ATTN_SMEM_BYTES>>>(
            q_h, q_l, k_h, k_l, v_h, v_l, att);
    }
    // 4) split attention output, then output projection (tensor cores)
    {
        int n4 = M * DMODEL;
        split_kernel<<<n4 / 1024, 256>>>(att, at_h, at_l, n4);
        dim3 grid(DMODEL / 128, M / 128);      // (8, 32)
        gemm_mma_kernel<<<grid, 256, GEMM_SMEM_BYTES>>>(
            at_h, at_l, wp_h, wp_l, b_proj, out, M, DMODEL, DMODEL);
    }
}

// round 9
// speedup vs baseline: 4.0761x; 1.0101x over previous
#include <cuda_runtime.h>
#include <cuda_bf16.h>
#include <math.h>

// Problem constants (fixed by the reference)
#define BATCH 2
#define SEQ   2048
#define DMODEL 1024
#define NHEAD 16
#define HD    64          // head dim
#define QKV_ROW (3*DMODEL)

typedef unsigned int uint32;

// ---- mma / ldmatrix / cp.async wrappers -----------------------------------
__device__ __forceinline__ void ldsm_x4(uint32 r[4], uint32 addr) {
    asm volatile("ldmatrix.sync.aligned.m8n8.x4.shared.b16 {%0,%1,%2,%3}, [%4];"
                 : "=r"(r[0]), "=r"(r[1]), "=r"(r[2]), "=r"(r[3]) : "r"(addr));
}
__device__ __forceinline__ void ldsm_x4_t(uint32 r[4], uint32 addr) {
    asm volatile("ldmatrix.sync.aligned.m8n8.x4.trans.shared.b16 {%0,%1,%2,%3}, [%4];"
                 : "=r"(r[0]), "=r"(r[1]), "=r"(r[2]), "=r"(r[3]) : "r"(addr));
}
__device__ __forceinline__ void mma_bf16(float d[4], const uint32 a[4],
                                         uint32 b0, uint32 b1) {
    asm volatile(
        "mma.sync.aligned.m16n8k16.row.col.f32.bf16.bf16.f32 "
        "{%0,%1,%2,%3}, {%4,%5,%6,%7}, {%8,%9}, {%10,%11,%12,%13};"
        : "=f"(d[0]), "=f"(d[1]), "=f"(d[2]), "=f"(d[3])
        : "r"(a[0]), "r"(a[1]), "r"(a[2]), "r"(a[3]),
          "r"(b0), "r"(b1),
          "f"(d[0]), "f"(d[1]), "f"(d[2]), "f"(d[3]));
}
__device__ __forceinline__ void cp16(uint32 smem_addr, const void* gptr) {
    asm volatile("cp.async.ca.shared.global [%0], [%1], 16;\n"
                 :: "r"(smem_addr), "l"(gptr));
}
__device__ __forceinline__ void cp_commit() {
    asm volatile("cp.async.commit_group;\n");
}
template<int N> __device__ __forceinline__ void cp_wait() {
    asm volatile("cp.async.wait_group %0;\n" :: "n"(N));
}

// split one float pair -> packed bf16x2 hi + packed bf16x2 lo
__device__ __forceinline__ void split2(float x, float y, uint32 &hi, uint32 &lo) {
    __nv_bfloat162 h2 = __floats2bfloat162_rn(x, y);
    hi = *reinterpret_cast<uint32*>(&h2);
    float rx = x - __bfloat162float(h2.x);
    float ry = y - __bfloat162float(h2.y);
    __nv_bfloat162 l2 = __floats2bfloat162_rn(rx, ry);
    lo = *reinterpret_cast<uint32*>(&l2);
}

// Scratch (allocation-free rule: __device__ globals)
__device__ __nv_bfloat16 g_hid_h[(size_t)BATCH*SEQ*DMODEL];
__device__ __nv_bfloat16 g_hid_l[(size_t)BATCH*SEQ*DMODEL];
__device__ __nv_bfloat16 g_wa_h[(size_t)DMODEL*3*DMODEL];
__device__ __nv_bfloat16 g_wa_l[(size_t)DMODEL*3*DMODEL];
__device__ __nv_bfloat16 g_wp_h[(size_t)DMODEL*DMODEL];
__device__ __nv_bfloat16 g_wp_l[(size_t)DMODEL*DMODEL];
__device__ __nv_bfloat16 g_at_h[(size_t)BATCH*SEQ*DMODEL];
__device__ __nv_bfloat16 g_at_l[(size_t)BATCH*SEQ*DMODEL];
// head-major [B][H][S][HD] bf16 splits of q (pre-scaled by 1/8), k, v
#define HEADS_ELEMS ((size_t)BATCH*NHEAD*SEQ*HD)
__device__ __nv_bfloat16 g_q_h[HEADS_ELEMS];
__device__ __nv_bfloat16 g_q_l[HEADS_ELEMS];
__device__ __nv_bfloat16 g_k_h[HEADS_ELEMS];
__device__ __nv_bfloat16 g_k_l[HEADS_ELEMS];
__device__ __nv_bfloat16 g_v_h[HEADS_ELEMS];
__device__ __nv_bfloat16 g_v_l[HEADS_ELEMS];

// ---------------------------------------------------------------------------
// fp32 -> (bf16 hi, bf16 lo) split (flat arrays).
// ---------------------------------------------------------------------------
__global__ __launch_bounds__(256)
void split_kernel(const float* __restrict__ x,
                  __nv_bfloat16* __restrict__ hi,
                  __nv_bfloat16* __restrict__ lo, int n)
{
    int i = (blockIdx.x * 256 + threadIdx.x) * 4;
    if (i >= n) return;
    float4 v = *(const float4*)&x[i];
    uint32 h0, l0, h1, l1;
    split2(v.x, v.y, h0, l0);
    split2(v.z, v.w, h1, l1);
    *(uint32*)&hi[i]     = h0;
    *(uint32*)&hi[i + 2] = h1;
    *(uint32*)&lo[i]     = l0;
    *(uint32*)&lo[i + 2] = l1;
}

// ---------------------------------------------------------------------------
// Tensor-core GEMM (bf16 3-term split, fp32 accumulate), cp.async double
// buffered, term-pass-ordered mma (no back-to-back same-accumulator mma).
// MODE 0: epilogue = bias + fp32 store to C.
// MODE 1: epilogue = bias, q-scale, bf16 hi/lo split, head-major scatter to
//         Q/K/V arrays (N must be 3*DMODEL; C unused).
// BM=128, BN=128, BK=32, 256 threads / 8 warps (4m x 2n), warp tile 32x64.
// ---------------------------------------------------------------------------
#define GEMM_SMEM_BYTES (4736 * 16)
template<int MODE>
__global__ __launch_bounds__(256, 1)
void gemm_mma_kernel(const __nv_bfloat16* __restrict__ Ah,
                     const __nv_bfloat16* __restrict__ Al,
                     const __nv_bfloat16* __restrict__ Wh,
                     const __nv_bfloat16* __restrict__ Wl,
                     const float* __restrict__ bias,
                     float* __restrict__ C,
                     __nv_bfloat16* __restrict__ Qh, __nv_bfloat16* __restrict__ Ql,
                     __nv_bfloat16* __restrict__ Kh, __nv_bfloat16* __restrict__ Kl,
                     __nv_bfloat16* __restrict__ Vh, __nv_bfloat16* __restrict__ Vl,
                     int M, int N, int K)
{
    extern __shared__ uint4 dsm[];
    uint32 base = (uint32)__cvta_generic_to_shared(dsm);
    const uint32 oAh = 0, oAl = 20480, oWh = 40960, oWl = 58368;
    const uint32 stA = 10240, stW = 8704;   // per-stage byte strides

    const int tid  = threadIdx.x;
    const int lane = tid & 31;
    const int wid  = tid >> 5;
    const int warp_m = wid & 3;
    const int warp_n = wid >> 2;
    const int row0 = blockIdx.y * 128;
    const int col0 = blockIdx.x * 128;

    // ldmatrix lane offsets
    const int j  = lane & 7;
    const int q  = lane >> 3;
    const int a_row_off = j + (q & 1) * 8;
    const int a_chk_off = q >> 1;
    uint32 aOff[2];
    #pragma unroll
    for (int ma = 0; ma < 2; ma++) {
        int r = warp_m * 32 + ma * 16 + a_row_off;
        aOff[ma] = (uint32)(r * 5 + a_chk_off) * 16;
    }
    uint32 wOff[4];
    #pragma unroll
    for (int nb = 0; nb < 4; nb++) {
        int k = j + (q & 1) * 8;
        int chk = (warp_n * 64 + nb * 16) / 8 + (q >> 1);
        wOff[nb] = (uint32)(k * 17 + chk) * 16;
    }

    // loader coordinates
    int aR[2], aC[2], wR[2], wC[2];
    #pragma unroll
    for (int t = 0; t < 2; t++) {
        int id = tid + t * 256;
        aR[t] = id >> 2;  aC[t] = id & 3;
        wR[t] = id >> 4;  wC[t] = id & 15;
    }

    float acc[2][8][4];
    #pragma unroll
    for (int ma = 0; ma < 2; ma++)
        #pragma unroll
        for (int na = 0; na < 8; na++)
            #pragma unroll
            for (int i = 0; i < 4; i++)
                acc[ma][na][i] = 0.f;

    const int nkt = K / 32;
    // prologue: stage 0
    #pragma unroll
    for (int t = 0; t < 2; t++) {
        cp16(base + oAh + (uint32)(aR[t] * 5 + aC[t]) * 16,
             &Ah[(size_t)(row0 + aR[t]) * K + aC[t] * 8]);
        cp16(base + oAl + (uint32)(aR[t] * 5 + aC[t]) * 16,
             &Al[(size_t)(row0 + aR[t]) * K + aC[t] * 8]);
        cp16(base + oWh + (uint32)(wR[t] * 17 + wC[t]) * 16,
             &Wh[(size_t)(wR[t]) * N + col0 + wC[t] * 8]);
        cp16(base + oWl + (uint32)(wR[t] * 17 + wC[t]) * 16,
             &Wl[(size_t)(wR[t]) * N + col0 + wC[t] * 8]);
    }
    cp_commit();

    for (int kt = 0; kt < nkt; kt++) {
        if (kt + 1 < nkt) {
            uint32 st = (uint32)((kt + 1) & 1);
            int k0n = (kt + 1) * 32;
            #pragma unroll
            for (int t = 0; t < 2; t++) {
                cp16(base + oAh + st * stA + (uint32)(aR[t] * 5 + aC[t]) * 16,
                     &Ah[(size_t)(row0 + aR[t]) * K + k0n + aC[t] * 8]);
                cp16(base + oAl + st * stA + (uint32)(aR[t] * 5 + aC[t]) * 16,
                     &Al[(size_t)(row0 + aR[t]) * K + k0n + aC[t] * 8]);
                cp16(base + oWh + st * stW + (uint32)(wR[t] * 17 + wC[t]) * 16,
                     &Wh[(size_t)(k0n + wR[t]) * N + col0 + wC[t] * 8]);
                cp16(base + oWl + st * stW + (uint32)(wR[t] * 17 + wC[t]) * 16,
                     &Wl[(size_t)(k0n + wR[t]) * N + col0 + wC[t] * 8]);
            }
            cp_commit();
            cp_wait<1>();
        } else {
            cp_wait<0>();
        }
        __syncthreads();

        uint32 st = (uint32)(kt & 1);
        uint32 bAh = base + oAh + st * stA;
        uint32 bAl = base + oAl + st * stA;
        uint32 bWh = base + oWh + st * stW;
        uint32 bWl = base + oWl + st * stW;

        #pragma unroll
        for (int ks = 0; ks < 2; ks++) {
            uint32 ah[2][4], al[2][4], bh[4][4], bl[4][4];
            ldsm_x4(ah[0], bAh + aOff[0] + ks * 32);
            ldsm_x4(ah[1], bAh + aOff[1] + ks * 32);
            ldsm_x4(al[0], bAl + aOff[0] + ks * 32);
            ldsm_x4(al[1], bAl + aOff[1] + ks * 32);
            #pragma unroll
            for (int nb = 0; nb < 4; nb++) {
                ldsm_x4_t(bh[nb], bWh + wOff[nb] + ks * 4352);  // +16 k * 272B
                ldsm_x4_t(bl[nb], bWl + wOff[nb] + ks * 4352);
            }
            // pass 1: Ah*Wh — 16 consecutive mma, all distinct accumulators
            #pragma unroll
            for (int nb = 0; nb < 4; nb++)
                #pragma unroll
                for (int ma = 0; ma < 2; ma++) {
                    mma_bf16(acc[ma][2*nb],   ah[ma], bh[nb][0], bh[nb][1]);
                    mma_bf16(acc[ma][2*nb+1], ah[ma], bh[nb][2], bh[nb][3]);
                }
            // pass 2: Ah*Wl
            #pragma unroll
            for (int nb = 0; nb < 4; nb++)
                #pragma unroll
                for (int ma = 0; ma < 2; ma++) {
                    mma_bf16(acc[ma][2*nb],   ah[ma], bl[nb][0], bl[nb][1]);
                    mma_bf16(acc[ma][2*nb+1], ah[ma], bl[nb][2], bl[nb][3]);
                }
            // pass 3: Al*Wh
            #pragma unroll
            for (int nb = 0; nb < 4; nb++)
                #pragma unroll
                for (int ma = 0; ma < 2; ma++) {
                    mma_bf16(acc[ma][2*nb],   al[ma], bh[nb][0], bh[nb][1]);
                    mma_bf16(acc[ma][2*nb+1], al[ma], bh[nb][2], bh[nb][3]);
                }
        }
        __syncthreads();
    }

    // ---- epilogue ----
    int r_base = row0 + warp_m * 32 + (lane >> 2);
    int c_base = col0 + warp_n * 64 + (lane & 3) * 2;
    #pragma unroll
    for (int ma = 0; ma < 2; ma++) {
        #pragma unroll
        for (int na = 0; na < 8; na++) {
            int c = c_base + na * 8;
            float bx = bias[c], by = bias[c + 1];
            #pragma unroll
            for (int half = 0; half < 2; half++) {
                int r = r_base + ma * 16 + half * 8;
                float vx = acc[ma][na][2 * half + 0] + bx;
                float vy = acc[ma][na][2 * half + 1] + by;
                if (MODE == 0) {
                    *(float2*)&C[(size_t)r * N + c] = make_float2(vx, vy);
                } else {
                    int arr = c >> 10;               // 0=q 1=k 2=v
                    int hh  = (c >> 6) & 15;
                    int dd  = c & 63;
                    int bb  = r >> 11, ss = r & 2047;
                    size_t dst = (((size_t)(bb * NHEAD + hh)) * SEQ + ss) * HD + dd;
                    if (arr == 0) { vx *= 0.125f; vy *= 0.125f; }
                    uint32 hi, lo;
                    split2(vx, vy, hi, lo);
                    __nv_bfloat16* ph = (arr == 0) ? Qh : (arr == 1) ? Kh : Vh;
                    __nv_bfloat16* pl = (arr == 0) ? Ql : (arr == 1) ? Kl : Vl;
                    *(uint32*)&ph[dst] = hi;
                    *(uint32*)&pl[dst] = lo;
                }
            }
        }
    }
}

// ---------------------------------------------------------------------------
// MMA causal flash attention (bf16 3-term splits, fp32 softmax/accum),
// term-pass-ordered mma; epilogue writes bf16 hi/lo split directly.
// BM=128 q rows/block, BN=64 keys/tile, 8 warps (warp = 16 q rows).
// ---------------------------------------------------------------------------
#define ATTN_SMEM_BYTES (2 * 36864)
__global__ __launch_bounds__(256, 1)
void attn_mma_kernel(const __nv_bfloat16* __restrict__ Qh,
                     const __nv_bfloat16* __restrict__ Ql,
                     const __nv_bfloat16* __restrict__ Kh,
                     const __nv_bfloat16* __restrict__ Kl,
                     const __nv_bfloat16* __restrict__ Vh,
                     const __nv_bfloat16* __restrict__ Vl,
                     __nv_bfloat16* __restrict__ Oh,
                     __nv_bfloat16* __restrict__ Ol)
{
    extern __shared__ uint4 dsm[];
    uint32 smem_u = (uint32)__cvta_generic_to_shared(dsm);

    const int tid  = threadIdx.x;
    const int lane = tid & 31;
    const int wq   = tid >> 5;
    const int qt = (int)gridDim.x - 1 - (int)blockIdx.x;
    const int h = blockIdx.y, b = blockIdx.z;
    const int q0 = qt * 128;
    const size_t headoff = ((size_t)(b * NHEAD + h)) * SEQ * HD;

    const int gid = lane >> 2;           // 0..7
    const int tig = lane & 3;            // 0..3
    const int row0 = q0 + wq * 16 + gid; // absolute q row (c0/c1); row1 = row0+8

    // ---- Q fragments straight from global ----
    uint32 qh[4][4], ql[4][4];
    {
        const __nv_bfloat16* Qhb = Qh + headoff;
        const __nv_bfloat16* Qlb = Ql + headoff;
        #pragma unroll
        for (int ks = 0; ks < 4; ks++) {
            int kc = ks * 16 + 2 * tig;
            qh[ks][0] = *(const uint32*)&Qhb[(size_t)row0 * HD + kc];
            qh[ks][1] = *(const uint32*)&Qhb[(size_t)(row0 + 8) * HD + kc];
            qh[ks][2] = *(const uint32*)&Qhb[(size_t)row0 * HD + kc + 8];
            qh[ks][3] = *(const uint32*)&Qhb[(size_t)(row0 + 8) * HD + kc + 8];
            ql[ks][0] = *(const uint32*)&Qlb[(size_t)row0 * HD + kc];
            ql[ks][1] = *(const uint32*)&Qlb[(size_t)(row0 + 8) * HD + kc];
            ql[ks][2] = *(const uint32*)&Qlb[(size_t)row0 * HD + kc + 8];
            ql[ks][3] = *(const uint32*)&Qlb[(size_t)(row0 + 8) * HD + kc + 8];
        }
    }

    // ldmatrix lane-invariant offsets
    const uint32 kOffBase = (uint32)((((lane >> 4) << 3) + (lane & 7)) * 144
                                     + ((lane >> 3) & 1) * 16);
    const uint32 vOffBase = (uint32)(((lane & 7) + (((lane >> 3) & 1) << 3)) * 144
                                     + (lane >> 4) * 16);

    float o[8][4];
    #pragma unroll
    for (int t = 0; t < 8; t++)
        #pragma unroll
        for (int i = 0; i < 4; i++) o[t][i] = 0.f;
    float m0 = -INFINITY, m1 = -INFINITY, l0 = 0.f, l1 = 0.f;

    const __nv_bfloat16* kvsrc[4] = {Kh + headoff, Kl + headoff,
                                     Vh + headoff, Vl + headoff};
    const int ntiles = 2 * (qt + 1);

    // tile loader: 8 x cp16 per thread
    {
        #pragma unroll
        for (int t = 0; t < 8; t++) {
            int id = tid + t * 256;
            int arr = id >> 9;
            int r = (id >> 3) & 63;
            int c = id & 7;
            cp16(smem_u + (uint32)(arr * 9216 + r * 144 + c * 16),
                 kvsrc[arr] + (size_t)r * HD + c * 8);
        }
        cp_commit();
    }

    for (int tt = 0; tt < ntiles; tt++) {
        int kb = tt * 64;
        if (tt + 1 < ntiles) {
            uint32 stn = (uint32)((tt + 1) & 1) * 36864;
            int kbn = kb + 64;
            #pragma unroll
            for (int t = 0; t < 8; t++) {
                int id = tid + t * 256;
                int arr = id >> 9;
                int r = (id >> 3) & 63;
                int c = id & 7;
                cp16(smem_u + stn + (uint32)(arr * 9216 + r * 144 + c * 16),
                     kvsrc[arr] + (size_t)(kbn + r) * HD + c * 8);
            }
            cp_commit();
            cp_wait<1>();
        } else {
            cp_wait<0>();
        }
        __syncthreads();

        uint32 stb = smem_u + (uint32)(tt & 1) * 36864;
        uint32 khb = stb, klb = stb + 9216, vhb = stb + 18432, vlb = stb + 27648;

        // ---- S = Q K^T (3-term split), term-pass ordered ----
        float s[8][4];
        #pragma unroll
        for (int t = 0; t < 8; t++)
            #pragma unroll
            for (int i = 0; i < 4; i++) s[t][i] = 0.f;

        #pragma unroll
        for (int ks = 0; ks < 4; ks++) {
            uint32 bh[4][4], bl[4][4];
            #pragma unroll
            for (int g = 0; g < 4; g++) {
                ldsm_x4(bh[g], khb + (uint32)(g * 2304 + ks * 32) + kOffBase);
                ldsm_x4(bl[g], klb + (uint32)(g * 2304 + ks * 32) + kOffBase);
            }
            // pass 1: qh*kh — 8 consecutive mma, distinct accumulators
            #pragma unroll
            for (int g = 0; g < 4; g++) {
                mma_bf16(s[2*g],   qh[ks], bh[g][0], bh[g][1]);
                mma_bf16(s[2*g+1], qh[ks], bh[g][2], bh[g][3]);
            }
            // pass 2: qh*kl
            #pragma unroll
            for (int g = 0; g < 4; g++) {
                mma_bf16(s[2*g],   qh[ks], bl[g][0], bl[g][1]);
                mma_bf16(s[2*g+1], qh[ks], bl[g][2], bl[g][3]);
            }
            // pass 3: ql*kh
            #pragma unroll
            for (int g = 0; g < 4; g++) {
                mma_bf16(s[2*g],   ql[ks], bh[g][0], bh[g][1]);
                mma_bf16(s[2*g+1], ql[ks], bh[g][2], bh[g][3]);
            }
        }

        // ---- causal mask (diagonal tiles only) ----
        if (kb + 63 > q0 + wq * 16) {
            #pragma unroll
            for (int t = 0; t < 8; t++) {
                int key = kb + t * 8 + 2 * tig;
                if (key     > row0)     s[t][0] = -INFINITY;
                if (key + 1 > row0)     s[t][1] = -INFINITY;
                if (key     > row0 + 8) s[t][2] = -INFINITY;
                if (key + 1 > row0 + 8) s[t][3] = -INFINITY;
            }
        }

        // ---- online softmax ----
        float r0 = -INFINITY, r1 = -INFINITY;
        #pragma unroll
        for (int t = 0; t < 8; t++) {
            r0 = fmaxf(r0, fmaxf(s[t][0], s[t][1]));
            r1 = fmaxf(r1, fmaxf(s[t][2], s[t][3]));
        }
        r0 = fmaxf(r0, __shfl_xor_sync(0xffffffffu, r0, 1));
        r0 = fmaxf(r0, __shfl_xor_sync(0xffffffffu, r0, 2));
        r1 = fmaxf(r1, __shfl_xor_sync(0xffffffffu, r1, 1));
        r1 = fmaxf(r1, __shfl_xor_sync(0xffffffffu, r1, 2));
        float mn0 = fmaxf(m0, r0), mn1 = fmaxf(m1, r1);
        float c0 = __expf(m0 - mn0), c1 = __expf(m1 - mn1);
        m0 = mn0; m1 = mn1;
        l0 *= c0;  l1 *= c1;
        #pragma unroll
        for (int t = 0; t < 8; t++) {
            s[t][0] = __expf(s[t][0] - m0);
            s[t][1] = __expf(s[t][1] - m0);
            s[t][2] = __expf(s[t][2] - m1);
            s[t][3] = __expf(s[t][3] - m1);
            l0 += s[t][0] + s[t][1];
            l1 += s[t][2] + s[t][3];
        }
        #pragma unroll
        for (int t = 0; t < 8; t++) {
            o[t][0] *= c0; o[t][1] *= c0;
            o[t][2] *= c1; o[t][3] *= c1;
        }

        // ---- pack P (C-frag == A-frag identity), hi/lo split ----
        uint32 ph[4][4], pl[4][4];
        #pragma unroll
        for (int kk = 0; kk < 4; kk++) {
            split2(s[2*kk][0],   s[2*kk][1],   ph[kk][0], pl[kk][0]);
            split2(s[2*kk][2],   s[2*kk][3],   ph[kk][1], pl[kk][1]);
            split2(s[2*kk+1][0], s[2*kk+1][1], ph[kk][2], pl[kk][2]);
            split2(s[2*kk+1][2], s[2*kk+1][3], ph[kk][3], pl[kk][3]);
        }

        // ---- O += P V (3-term split), term-pass ordered ----
        #pragma unroll
        for (int kk = 0; kk < 4; kk++) {
            uint32 vh4[4][4], vl4[4][4];
            #pragma unroll
            for (int g = 0; g < 4; g++) {
                ldsm_x4_t(vh4[g], vhb + (uint32)(kk * 2304 + g * 32) + vOffBase);
                ldsm_x4_t(vl4[g], vlb + (uint32)(kk * 2304 + g * 32) + vOffBase);
            }
            #pragma unroll
            for (int g = 0; g < 4; g++) {
                mma_bf16(o[2*g],   ph[kk], vh4[g][0], vh4[g][1]);
                mma_bf16(o[2*g+1], ph[kk], vh4[g][2], vh4[g][3]);
            }
            #pragma unroll
            for (int g = 0; g < 4; g++) {
                mma_bf16(o[2*g],   ph[kk], vl4[g][0], vl4[g][1]);
                mma_bf16(o[2*g+1], ph[kk], vl4[g][2], vl4[g][3]);
            }
            #pragma unroll
            for (int g = 0; g < 4; g++) {
                mma_bf16(o[2*g],   pl[kk], vh4[g][0], vh4[g][1]);
                mma_bf16(o[2*g+1], pl[kk], vh4[g][2], vh4[g][3]);
            }
        }
        __syncthreads();
    }

    // ---- finalize: reduce l across quad, normalize, split-store bf16 ----
    l0 += __shfl_xor_sync(0xffffffffu, l0, 1);
    l0 += __shfl_xor_sync(0xffffffffu, l0, 2);
    l1 += __shfl_xor_sync(0xffffffffu, l1, 1);
    l1 += __shfl_xor_sync(0xffffffffu, l1, 2);
    float i0 = 1.f / l0, i1 = 1.f / l1;
    #pragma unroll
    for (int t = 0; t < 8; t++) {
        int col = h * HD + t * 8 + 2 * tig;
        size_t d0 = ((size_t)(b * SEQ + row0)) * DMODEL + col;
        size_t d1 = ((size_t)(b * SEQ + row0 + 8)) * DMODEL + col;
        uint32 hi, lo;
        split2(o[t][0] * i0, o[t][1] * i0, hi, lo);
        *(uint32*)&Oh[d0] = hi;  *(uint32*)&Ol[d0] = lo;
        split2(o[t][2] * i1, o[t][3] * i1, hi, lo);
        *(uint32*)&Oh[d1] = hi;  *(uint32*)&Ol[d1] = lo;
    }
}

// ---------------------------------------------------------------------------
// Launch
// ---------------------------------------------------------------------------
extern "C" void kernel_launch(void* const* d_in, const int* in_sizes, int n_in,
                              void* d_out, int out_size)
{
    const float* hidden = (const float*)d_in[0];   // [B,S,D]
    const float* W_attn = (const float*)d_in[1];   // [D,3D]
    const float* b_attn = (const float*)d_in[2];   // [3D]
    const float* W_proj = (const float*)d_in[3];   // [D,D]
    const float* b_proj = (const float*)d_in[4];   // [D]
    float* out = (float*)d_out;                    // [B,S,D]

    __nv_bfloat16 *hid_h, *hid_l, *wa_h, *wa_l, *wp_h, *wp_l, *at_h, *at_l;
    __nv_bfloat16 *q_h, *q_l, *k_h, *k_l, *v_h, *v_l;
    cudaGetSymbolAddress((void**)&hid_h, g_hid_h);
    cudaGetSymbolAddress((void**)&hid_l, g_hid_l);
    cudaGetSymbolAddress((void**)&wa_h, g_wa_h);
    cudaGetSymbolAddress((void**)&wa_l, g_wa_l);
    cudaGetSymbolAddress((void**)&wp_h, g_wp_h);
    cudaGetSymbolAddress((void**)&wp_l, g_wp_l);
    cudaGetSymbolAddress((void**)&at_h, g_at_h);
    cudaGetSymbolAddress((void**)&at_l, g_at_l);
    cudaGetSymbolAddress((void**)&q_h, g_q_h);
    cudaGetSymbolAddress((void**)&q_l, g_q_l);
    cudaGetSymbolAddress((void**)&k_h, g_k_h);
    cudaGetSymbolAddress((void**)&k_l, g_k_l);
    cudaGetSymbolAddress((void**)&v_h, g_v_h);
    cudaGetSymbolAddress((void**)&v_l, g_v_l);

    cudaFuncSetAttribute(gemm_mma_kernel<0>,
                         cudaFuncAttributeMaxDynamicSharedMemorySize,
                         GEMM_SMEM_BYTES);
    cudaFuncSetAttribute(gemm_mma_kernel<1>,
                         cudaFuncAttributeMaxDynamicSharedMemorySize,
                         GEMM_SMEM_BYTES);
    cudaFuncSetAttribute(attn_mma_kernel,
                         cudaFuncAttributeMaxDynamicSharedMemorySize,
                         ATTN_SMEM_BYTES);

    const int M = BATCH * SEQ;   // 4096

    // 0) fp32 -> bf16 hi/lo splits of GEMM inputs
    {
        int n1 = M * DMODEL;
        split_kernel<<<n1 / 1024, 256>>>(hidden, hid_h, hid_l, n1);
        int n2 = DMODEL * 3 * DMODEL;
        split_kernel<<<n2 / 1024, 256>>>(W_attn, wa_h, wa_l, n2);
        int n3 = DMODEL * DMODEL;
        split_kernel<<<n3 / 1024, 256>>>(W_proj, wp_h, wp_l, n3);
    }
    // 1) QKV projection (tensor cores) -> fused head-major bf16 hi/lo split
    {
        dim3 grid(3 * DMODEL / 128, M / 128);  // (24, 32)
        gemm_mma_kernel<1><<<grid, 256, GEMM_SMEM_BYTES>>>(
            hid_h, hid_l, wa_h, wa_l, b_attn, nullptr,
            q_h, q_l, k_h, k_l, v_h, v_l, M, 3 * DMODEL, DMODEL);
    }
    // 2) causal attention (tensor cores) -> bf16 hi/lo output split
    {
        dim3 grid(SEQ / 128, NHEAD, BATCH);    // (16, 16, 2)
        attn_mma_kernel<<<grid, 256, ATTN_SMEM_BYTES>>>(
            q_h, q_l, k_h, k_l, v_h, v_l, at_h, at_l);
    }
    // 3) output projection (tensor cores) -> fp32 out
    {
        dim3 grid(DMODEL / 128, M / 128);      // (8, 32)
        gemm_mma_kernel<0><<<grid, 256, GEMM_SMEM_BYTES>>>(
            at_h, at_l, wp_h, wp_l, b_proj, out,
            nullptr, nullptr, nullptr, nullptr, nullptr, nullptr,
            M, DMODEL, DMODEL);
    }
}